// round 6
// baseline (speedup 1.0000x reference)
#include <cuda_runtime.h>
#include <cuda_fp16.h>
#include <math.h>
#include <stddef.h>
#include <stdint.h>

#define SEQ    2048
#define DIMM   2048
#define HEADS  16
#define DHEAD  128
#define QKVN   2304
#define K2DIM  1024          // K/2 half2 units per row (K=2048 everywhere)
#define EPSF   1e-5f
#define MASKVF 1e-10f
#define SCALEF 0.08838834764831845f

// ---------------- scratch ---------------------------------------------------
__device__ unsigned g_xnh[SEQ * K2DIM];      // RMSNorm out, half2 hi
__device__ unsigned g_xnl[SEQ * K2DIM];      // half2 lo
__device__ unsigned g_wch[QKVN * K2DIM];     // [wq|wk|wv]^T hi (q pre-scaled)
__device__ unsigned g_wcl[QKVN * K2DIM];
__device__ unsigned g_woh[DIMM * K2DIM];     // wo^T hi
__device__ unsigned g_wol[DIMM * K2DIM];
__device__ uint4    g_qh4[HEADS * 128 * 8 * 32];   // Q fragments hi
__device__ uint4    g_ql4[HEADS * 128 * 8 * 32];
__device__ unsigned g_kt2h[64 * SEQ];        // K^T half2-packed along d
__device__ unsigned g_kt2l[64 * SEQ];
__device__ float    g_v[SEQ * DHEAD];        // V dense fp32
__device__ unsigned g_vt2h[(SEQ / 2) * DHEAD];
__device__ unsigned g_vt2l[(SEQ / 2) * DHEAD];
__device__ unsigned g_aoh[SEQ * K2DIM];      // attention out hi
__device__ unsigned g_aol[SEQ * K2DIM];
__device__ float    g_vsuf[SEQ * DHEAD];
__device__ float    g_vpart[16 * DHEAD];

// ---------------- helpers ----------------------------------------------------
__device__ __forceinline__ void cvt_h2(float x0, float x1, unsigned& h, unsigned& l) {
    __half2 hh = __floats2half2_rn(x0, x1);
    __half2 ll = __floats2half2_rn(x0 - __low2float(hh), x1 - __high2float(hh));
    h = *reinterpret_cast<unsigned*>(&hh);
    l = *reinterpret_cast<unsigned*>(&ll);
}
#define MMA_F16(Cacc, Av, Bv)                                               \
    asm volatile("mma.sync.aligned.m16n8k16.row.col.f32.f16.f16.f32 "       \
        "{%0,%1,%2,%3}, {%4,%5,%6,%7}, {%8,%9}, {%0,%1,%2,%3};"             \
        : "+f"((Cacc)[0]), "+f"((Cacc)[1]), "+f"((Cacc)[2]), "+f"((Cacc)[3])\
        : "r"((Av).x), "r"((Av).y), "r"((Av).z), "r"((Av).w),               \
          "r"((Bv).x), "r"((Bv).y))

// ---------------- RMSNorm -> half2 hi/lo planes ------------------------------
__global__ void rmsnorm_split_kernel(const float* __restrict__ x,
                                     const float* __restrict__ gamma) {
    int row = blockIdx.x;
    const float* xr = x + (size_t)row * DIMM;
    float ss = 0.f;
    for (int i = threadIdx.x; i < DIMM; i += 256) { float v = xr[i]; ss += v * v; }
    __shared__ float red[8];
    #pragma unroll
    for (int o = 16; o; o >>= 1) ss += __shfl_xor_sync(0xffffffffu, ss, o);
    if ((threadIdx.x & 31) == 0) red[threadIdx.x >> 5] = ss;
    __syncthreads();
    if (threadIdx.x < 32) {
        float v = (threadIdx.x < 8) ? red[threadIdx.x] : 0.f;
        #pragma unroll
        for (int o = 4; o; o >>= 1) v += __shfl_xor_sync(0xffffffffu, v, o);
        if (threadIdx.x == 0) red[0] = v;
    }
    __syncthreads();
    float inv = rsqrtf(red[0] / (float)DIMM + EPSF);
    for (int u = threadIdx.x; u < K2DIM; u += 256) {
        float2 xv = *(const float2*)(xr + 2 * u);
        float2 gv = *(const float2*)(gamma + 2 * u);
        unsigned h, l;
        cvt_h2(xv.x * inv * gv.x, xv.y * inv * gv.y, h, l);
        g_xnh[(size_t)row * K2DIM + u] = h;
        g_xnl[(size_t)row * K2DIM + u] = l;
    }
}

// ---------------- transpose + split: dst[n][k/2 half2] = src[k][n] * scale ----
__global__ void transpose_split_kernel(const float* __restrict__ src,
                                       unsigned* __restrict__ dh,
                                       unsigned* __restrict__ dl,
                                       int C, float scale) {
    __shared__ float tile[32][33];
    int bx = blockIdx.x * 32, by = blockIdx.y * 32;   // bx: n, by: k
    int tx = threadIdx.x, ty = threadIdx.y;           // 32 x 8
    #pragma unroll
    for (int j = 0; j < 32; j += 8)
        tile[ty + j][tx] = src[(size_t)(by + ty + j) * C + bx + tx];
    __syncthreads();
    int ul = tx & 15, nb = ty * 2 + (tx >> 4);
    #pragma unroll
    for (int rep = 0; rep < 2; rep++) {
        int nl = nb + rep * 16;
        float v0 = tile[2 * ul][nl] * scale;
        float v1 = tile[2 * ul + 1][nl] * scale;
        unsigned h, l;
        cvt_h2(v0, v1, h, l);
        size_t idx = (size_t)(bx + nl) * K2DIM + (by >> 1) + ul;
        dh[idx] = h; dl[idx] = l;
    }
}

// ---------------- fp16x3 GEMM on pre-split half2 planes ----------------------
// 128x128 tile, 8 warps (4m x 2n), K-stage 32, double-buffered, pure-copy stage.
// EPI=0: write fp32 C.  EPI=1: QKV epilogue (Q fragments / K planes / V dense).
template <int EPI>
__global__ __launch_bounds__(256) void gemm_h2_kernel(
    const unsigned* __restrict__ Ah, const unsigned* __restrict__ Al,
    const unsigned* __restrict__ Bh, const unsigned* __restrict__ Bl,
    float* __restrict__ C, int N)
{
    extern __shared__ unsigned smu[];
    const int tid = threadIdx.x, lane = tid & 31, warp = tid >> 5;
    const int m0 = blockIdx.y << 7, n0 = blockIdx.x << 7;
    const int wm = warp >> 1, wn = warp & 1;
    const int gid = lane >> 2, tig = lane & 3;

    float acc[2][8][4];
    #pragma unroll
    for (int mf = 0; mf < 2; mf++)
        #pragma unroll
        for (int nf = 0; nf < 8; nf++)
            #pragma unroll
            for (int q = 0; q < 4; q++) acc[mf][nf][q] = 0.f;

    unsigned rah[2][4], ral[2][4], rbh[4][2], rbl[4][2];
    const int arow = m0 + warp * 16 + gid;

    // prologue (stage 0)
    #pragma unroll
    for (int i = 0; i < 2; i++) {
        int u0 = 8 * i + tig;
        rah[i][0] = Ah[(size_t)arow * K2DIM + u0];
        rah[i][1] = Ah[(size_t)(arow + 8) * K2DIM + u0];
        rah[i][2] = Ah[(size_t)arow * K2DIM + u0 + 4];
        rah[i][3] = Ah[(size_t)(arow + 8) * K2DIM + u0 + 4];
        ral[i][0] = Al[(size_t)arow * K2DIM + u0];
        ral[i][1] = Al[(size_t)(arow + 8) * K2DIM + u0];
        ral[i][2] = Al[(size_t)arow * K2DIM + u0 + 4];
        ral[i][3] = Al[(size_t)(arow + 8) * K2DIM + u0 + 4];
    }
    #pragma unroll
    for (int j = 0; j < 4; j++) {
        int n = n0 + (warp + 8 * (j & 1)) * 8 + gid;
        int u0 = (j >> 1) * 8 + tig;
        rbh[j][0] = Bh[(size_t)n * K2DIM + u0];
        rbh[j][1] = Bh[(size_t)n * K2DIM + u0 + 4];
        rbl[j][0] = Bl[(size_t)n * K2DIM + u0];
        rbl[j][1] = Bl[(size_t)n * K2DIM + u0 + 4];
    }

    const int S = 64;   // 2048 / 32
    for (int s = 0; s < S; s++) {
        unsigned* buf = smu + (s & 1) * 8192;
        uint4* Ah4 = (uint4*)buf;
        uint4* Al4 = (uint4*)(buf + 2048);
        uint2* Bh2 = (uint2*)(buf + 4096);
        uint2* Bl2 = (uint2*)(buf + 6144);

        #pragma unroll
        for (int i = 0; i < 2; i++) {
            int slot = warp + 8 * i;
            Ah4[slot * 32 + lane] = make_uint4(rah[i][0], rah[i][1], rah[i][2], rah[i][3]);
            Al4[slot * 32 + lane] = make_uint4(ral[i][0], ral[i][1], ral[i][2], ral[i][3]);
        }
        #pragma unroll
        for (int j = 0; j < 4; j++) {
            int slot = (j >> 1) * 16 + warp + 8 * (j & 1);
            Bh2[slot * 32 + lane] = make_uint2(rbh[j][0], rbh[j][1]);
            Bl2[slot * 32 + lane] = make_uint2(rbl[j][0], rbl[j][1]);
        }
        __syncthreads();

        if (s + 1 < S) {
            const int ub = (s + 1) << 4;
            #pragma unroll
            for (int i = 0; i < 2; i++) {
                int u0 = ub + 8 * i + tig;
                rah[i][0] = Ah[(size_t)arow * K2DIM + u0];
                rah[i][1] = Ah[(size_t)(arow + 8) * K2DIM + u0];
                rah[i][2] = Ah[(size_t)arow * K2DIM + u0 + 4];
                rah[i][3] = Ah[(size_t)(arow + 8) * K2DIM + u0 + 4];
                ral[i][0] = Al[(size_t)arow * K2DIM + u0];
                ral[i][1] = Al[(size_t)(arow + 8) * K2DIM + u0];
                ral[i][2] = Al[(size_t)arow * K2DIM + u0 + 4];
                ral[i][3] = Al[(size_t)(arow + 8) * K2DIM + u0 + 4];
            }
            #pragma unroll
            for (int j = 0; j < 4; j++) {
                int n = n0 + (warp + 8 * (j & 1)) * 8 + gid;
                int u0 = ub + (j >> 1) * 8 + tig;
                rbh[j][0] = Bh[(size_t)n * K2DIM + u0];
                rbh[j][1] = Bh[(size_t)n * K2DIM + u0 + 4];
                rbl[j][0] = Bl[(size_t)n * K2DIM + u0];
                rbl[j][1] = Bl[(size_t)n * K2DIM + u0 + 4];
            }
        }

        #pragma unroll
        for (int kk = 0; kk < 2; kk++) {
            uint4 ah[2], al[2];
            #pragma unroll
            for (int mf = 0; mf < 2; mf++) {
                int slot = kk * 8 + wm * 2 + mf;
                ah[mf] = Ah4[slot * 32 + lane];
                al[mf] = Al4[slot * 32 + lane];
            }
            #pragma unroll
            for (int nf = 0; nf < 8; nf++) {
                int slot = kk * 16 + wn * 8 + nf;
                uint2 bh = Bh2[slot * 32 + lane];
                uint2 bl = Bl2[slot * 32 + lane];
                #pragma unroll
                for (int mf = 0; mf < 2; mf++) {
                    MMA_F16(acc[mf][nf], ah[mf], bh);
                    MMA_F16(acc[mf][nf], ah[mf], bl);
                    MMA_F16(acc[mf][nf], al[mf], bh);
                }
            }
        }
        __syncthreads();
    }

    if (EPI == 0) {
        #pragma unroll
        for (int mf = 0; mf < 2; mf++) {
            const int r0 = m0 + wm * 32 + mf * 16 + gid;
            #pragma unroll
            for (int nf = 0; nf < 8; nf++) {
                const int c = n0 + wn * 64 + nf * 8 + tig * 2;
                float2 v0, v1;
                v0.x = acc[mf][nf][0]; v0.y = acc[mf][nf][1];
                v1.x = acc[mf][nf][2]; v1.y = acc[mf][nf][3];
                *(float2*)(C + (size_t)r0 * N + c) = v0;
                *(float2*)(C + (size_t)(r0 + 8) * N + c) = v1;
            }
        }
    } else {
        const int bx = blockIdx.x;
        if (bx < 16) {
            // Q: write attention A-fragments directly (hi/lo)
            const int h = bx;
            #pragma unroll
            for (int mf = 0; mf < 2; mf++) {
                int rg = (m0 >> 4) + wm * 2 + mf;
                #pragma unroll
                for (int k2 = 0; k2 < 4; k2++) {
                    int kkg = wn * 4 + k2;
                    const float* e = acc[mf][2 * k2];
                    const float* o = acc[mf][2 * k2 + 1];
                    uint4 hv, lv;
                    cvt_h2(e[0], e[1], hv.x, lv.x);   // a0: row gid,   k tig*2
                    cvt_h2(e[2], e[3], hv.y, lv.y);   // a1: row gid+8
                    cvt_h2(o[0], o[1], hv.z, lv.z);   // a2: row gid,   k+8
                    cvt_h2(o[2], o[3], hv.w, lv.w);   // a3: row gid+8, k+8
                    size_t idx = ((size_t)(h * 128 + rg) * 8 + kkg) * 32 + lane;
                    g_qh4[idx] = hv;
                    g_ql4[idx] = lv;
                }
            }
        } else if (bx == 16) {
            // K: write transposed half2 planes
            #pragma unroll
            for (int mf = 0; mf < 2; mf++) {
                int j = m0 + wm * 32 + mf * 16 + gid;
                #pragma unroll
                for (int nf = 0; nf < 8; nf++) {
                    int d2 = wn * 32 + nf * 4 + tig;
                    unsigned h0, l0, h1, l1;
                    cvt_h2(acc[mf][nf][0], acc[mf][nf][1], h0, l0);
                    cvt_h2(acc[mf][nf][2], acc[mf][nf][3], h1, l1);
                    g_kt2h[d2 * SEQ + j] = h0;     g_kt2l[d2 * SEQ + j] = l0;
                    g_kt2h[d2 * SEQ + j + 8] = h1; g_kt2l[d2 * SEQ + j + 8] = l1;
                }
            }
        } else {
            // V: dense fp32
            #pragma unroll
            for (int mf = 0; mf < 2; mf++) {
                int j = m0 + wm * 32 + mf * 16 + gid;
                #pragma unroll
                for (int nf = 0; nf < 8; nf++) {
                    int d = wn * 64 + nf * 8 + tig * 2;
                    *(float2*)&g_v[(size_t)j * DHEAD + d] =
                        make_float2(acc[mf][nf][0], acc[mf][nf][1]);
                    *(float2*)&g_v[(size_t)(j + 8) * DHEAD + d] =
                        make_float2(acc[mf][nf][2], acc[mf][nf][3]);
                }
            }
        }
    }
}

// ---------------- V j-paired half2 planes (from dense V) ----------------------
__global__ void vprep_kernel() {
    int t = blockIdx.x * 256 + threadIdx.x;     // 131072
    int d = t & 127, j2 = t >> 7;
    float v0 = g_v[(size_t)(2 * j2) * DHEAD + d];
    float v1 = g_v[(size_t)(2 * j2 + 1) * DHEAD + d];
    unsigned h, l;
    cvt_h2(v0, v1, h, l);
    g_vt2h[j2 * DHEAD + d] = h;
    g_vt2l[j2 * DHEAD + d] = l;
}

// ---------------- V suffix sums (dense source) --------------------------------
__global__ void vpart_kernel() {
    int blk = blockIdx.x, d = threadIdx.x;
    float s = 0.f;
    #pragma unroll 8
    for (int r = 0; r < 128; r++)
        s += g_v[(size_t)(blk * 128 + r) * DHEAD + d];
    g_vpart[blk * DHEAD + d] = s;
}
__global__ void vsuf_kernel() {
    int blk = blockIdx.x, d = threadIdx.x;
    float acc = 0.f;
    for (int b = blk + 1; b < 16; b++) acc += g_vpart[b * DHEAD + d];
    #pragma unroll 4
    for (int r = 127; r >= 0; r--) {
        int row = blk * 128 + r;
        g_vsuf[(size_t)row * DHEAD + d] = acc;
        acc += g_v[(size_t)row * DHEAD + d];
    }
}

// ---------------- fp16x3 tensor-core flash attention ----------------------------
__global__ __launch_bounds__(256) void attn_mma_kernel(const float* __restrict__ pos_bias) {
    extern __shared__ float sm[];
    unsigned* Ku = (unsigned*)sm;
    unsigned* Kl = (unsigned*)(sm + 4608);
    unsigned* Vu = (unsigned*)(sm + 9216);
    unsigned* Vl = (unsigned*)(sm + 13568);
    unsigned* Pu = (unsigned*)(sm + 17920);
    unsigned* Pl = (unsigned*)(sm + 20224);
    float* srmax = sm + 22528;
    float* srsum = sm + 22656;

    const int h  = blockIdx.y;
    const int ib = gridDim.x - 1 - blockIdx.x;
    const int i0 = ib * 64;
    const int tid = threadIdx.x, lane = tid & 31, warp = tid >> 5;
    const int wm = warp >> 1, wn = warp & 1;
    const int gid = lane >> 2, tig = lane & 3;

    const int rg = (i0 >> 4) + wm;
    const size_t qbase = ((size_t)(h * 128 + rg) * 8) * 32 + lane;

    const int jl = tid & 63, cb = tid >> 6;
    const int r0g = i0 + wm * 16 + gid, r1g = r0g + 8;
    const int rl0 = wm * 16 + gid;

    float o[8][4];
    #pragma unroll
    for (int nf = 0; nf < 8; nf++)
        #pragma unroll
        for (int q = 0; q < 4; q++) o[nf][q] = 0.f;
    float m0 = -1e30f, m1 = -1e30f, l0 = 0.f, l1 = 0.f;

    for (int jb = 0; jb <= ib; jb++) {
        const int j0 = jb * 64;
        __syncthreads();
        #pragma unroll
        for (int it = 0; it < 16; it++) {
            int d2 = cb * 16 + it;
            Ku[d2 * 72 + jl] = g_kt2h[d2 * SEQ + j0 + jl];
            Kl[d2 * 72 + jl] = g_kt2l[d2 * SEQ + j0 + jl];
        }
        #pragma unroll
        for (int it = 0; it < 16; it++) {
            int idx = it * 256 + tid;
            int j2 = idx >> 7, d = idx & 127;
            Vu[j2 * 136 + d] = g_vt2h[(j0 / 2 + j2) * DHEAD + d];
            Vl[j2 * 136 + d] = g_vt2l[(j0 / 2 + j2) * DHEAD + d];
        }
        __syncthreads();

        float s[4][4];
        #pragma unroll
        for (int nf = 0; nf < 4; nf++)
            #pragma unroll
            for (int q = 0; q < 4; q++) s[nf][q] = 0.f;

        #pragma unroll
        for (int kk = 0; kk < 8; kk++) {
            uint4 qh = g_qh4[qbase + kk * 32];
            uint4 ql = g_ql4[qbase + kk * 32];
            const int kr0 = (kk * 8 + tig) * 72, kr1 = kr0 + 4 * 72;
            #pragma unroll
            for (int nf = 0; nf < 4; nf++) {
                int col = wn * 32 + nf * 8 + gid;
                uint2 bh = make_uint2(Ku[kr0 + col], Ku[kr1 + col]);
                uint2 bl = make_uint2(Kl[kr0 + col], Kl[kr1 + col]);
                MMA_F16(s[nf], qh, bh);
                MMA_F16(s[nf], qh, bl);
                MMA_F16(s[nf], ql, bh);
            }
        }

        const float* pb0 = pos_bias + ((size_t)h * SEQ + r0g) * SEQ + j0 + wn * 32 + tig * 2;
        const float* pb1 = pb0 + (size_t)8 * SEQ;
        #pragma unroll
        for (int nf = 0; nf < 4; nf++) {
            float2 b0 = *(const float2*)(pb0 + nf * 8);
            float2 b1 = *(const float2*)(pb1 + nf * 8);
            s[nf][0] += b0.x; s[nf][1] += b0.y;
            s[nf][2] += b1.x; s[nf][3] += b1.y;
        }
        if (jb == ib) {
            #pragma unroll
            for (int nf = 0; nf < 4; nf++) {
                int c = j0 + wn * 32 + nf * 8 + tig * 2;
                if (c > r0g)     s[nf][0] = -1e30f;
                if (c + 1 > r0g) s[nf][1] = -1e30f;
                if (c > r1g)     s[nf][2] = -1e30f;
                if (c + 1 > r1g) s[nf][3] = -1e30f;
            }
        }

        float rm0 = -1e30f, rm1 = -1e30f;
        #pragma unroll
        for (int nf = 0; nf < 4; nf++) {
            rm0 = fmaxf(rm0, fmaxf(s[nf][0], s[nf][1]));
            rm1 = fmaxf(rm1, fmaxf(s[nf][2], s[nf][3]));
        }
        rm0 = fmaxf(rm0, __shfl_xor_sync(0xffffffffu, rm0, 1));
        rm0 = fmaxf(rm0, __shfl_xor_sync(0xffffffffu, rm0, 2));
        rm1 = fmaxf(rm1, __shfl_xor_sync(0xffffffffu, rm1, 1));
        rm1 = fmaxf(rm1, __shfl_xor_sync(0xffffffffu, rm1, 2));
        srmax[wn * 64 + rl0] = rm0;
        srmax[wn * 64 + rl0 + 8] = rm1;
        __syncthreads();
        float bm0 = fmaxf(srmax[rl0], srmax[64 + rl0]);
        float bm1 = fmaxf(srmax[rl0 + 8], srmax[64 + rl0 + 8]);
        float mn0 = fmaxf(m0, bm0), mn1 = fmaxf(m1, bm1);
        float sc0 = __expf(m0 - mn0), sc1 = __expf(m1 - mn1);

        float rs0 = 0.f, rs1 = 0.f;
        #pragma unroll
        for (int nf = 0; nf < 4; nf++) {
            int pcol = wn * 16 + nf * 4 + tig;
            float p00 = __expf(s[nf][0] - mn0);
            float p01 = __expf(s[nf][1] - mn0);
            float p10 = __expf(s[nf][2] - mn1);
            float p11 = __expf(s[nf][3] - mn1);
            rs0 += p00 + p01; rs1 += p10 + p11;
            unsigned hw, lw;
            cvt_h2(p00, p01, hw, lw);
            Pu[rl0 * 36 + pcol] = hw; Pl[rl0 * 36 + pcol] = lw;
            cvt_h2(p10, p11, hw, lw);
            Pu[(rl0 + 8) * 36 + pcol] = hw; Pl[(rl0 + 8) * 36 + pcol] = lw;
        }
        rs0 += __shfl_xor_sync(0xffffffffu, rs0, 1);
        rs0 += __shfl_xor_sync(0xffffffffu, rs0, 2);
        rs1 += __shfl_xor_sync(0xffffffffu, rs1, 1);
        rs1 += __shfl_xor_sync(0xffffffffu, rs1, 2);
        srsum[wn * 64 + rl0] = rs0;
        srsum[wn * 64 + rl0 + 8] = rs1;
        __syncthreads();
        l0 = l0 * sc0 + srsum[rl0] + srsum[64 + rl0];
        l1 = l1 * sc1 + srsum[rl0 + 8] + srsum[64 + rl0 + 8];
        m0 = mn0; m1 = mn1;

        #pragma unroll
        for (int nf = 0; nf < 8; nf++) {
            o[nf][0] *= sc0; o[nf][1] *= sc0;
            o[nf][2] *= sc1; o[nf][3] *= sc1;
        }
        #pragma unroll
        for (int c = 0; c < 4; c++) {
            uint4 ah = make_uint4(Pu[rl0 * 36 + c * 8 + tig],
                                  Pu[(rl0 + 8) * 36 + c * 8 + tig],
                                  Pu[rl0 * 36 + c * 8 + 4 + tig],
                                  Pu[(rl0 + 8) * 36 + c * 8 + 4 + tig]);
            uint4 al = make_uint4(Pl[rl0 * 36 + c * 8 + tig],
                                  Pl[(rl0 + 8) * 36 + c * 8 + tig],
                                  Pl[rl0 * 36 + c * 8 + 4 + tig],
                                  Pl[(rl0 + 8) * 36 + c * 8 + 4 + tig]);
            const int vr0 = (c * 8 + tig) * 136, vr1 = vr0 + 4 * 136;
            #pragma unroll
            for (int nf = 0; nf < 8; nf++) {
                int dcol = wn * 64 + nf * 8 + gid;
                uint2 bh = make_uint2(Vu[vr0 + dcol], Vu[vr1 + dcol]);
                uint2 bl = make_uint2(Vl[vr0 + dcol], Vl[vr1 + dcol]);
                MMA_F16(o[nf], ah, bh);
                MMA_F16(o[nf], ah, bl);
                MMA_F16(o[nf], al, bh);
            }
        }
    }

    // finalize + write half2 hi/lo ao planes
    float cnt0 = (float)(SEQ - 1 - r0g), cnt1 = (float)(SEQ - 1 - r1g);
    float mf0 = fmaxf(m0, MASKVF), mf1 = fmaxf(m1, MASKVF);
    float wu0 = __expf(m0 - mf0),  wu1 = __expf(m1 - mf1);
    float wk0 = __expf(MASKVF - mf0), wk1 = __expf(MASKVF - mf1);
    float iZ0 = 1.f / (l0 * wu0 + cnt0 * wk0);
    float iZ1 = 1.f / (l1 * wu1 + cnt1 * wk1);
    #pragma unroll
    for (int nf = 0; nf < 8; nf++) {
        int dcol = wn * 64 + nf * 8 + tig * 2;
        float2 vs0 = *(const float2*)&g_vsuf[(size_t)r0g * DHEAD + dcol];
        float2 vs1 = *(const float2*)&g_vsuf[(size_t)r1g * DHEAD + dcol];
        float o00 = (o[nf][0] * wu0 + wk0 * vs0.x) * iZ0;
        float o01 = (o[nf][1] * wu0 + wk0 * vs0.y) * iZ0;
        float o10 = (o[nf][2] * wu1 + wk1 * vs1.x) * iZ1;
        float o11 = (o[nf][3] * wu1 + wk1 * vs1.y) * iZ1;
        unsigned hw, lw;
        size_t u = (size_t)(h * DHEAD + dcol) >> 1;
        cvt_h2(o00, o01, hw, lw);
        g_aoh[(size_t)r0g * K2DIM + u] = hw;
        g_aol[(size_t)r0g * K2DIM + u] = lw;
        cvt_h2(o10, o11, hw, lw);
        g_aoh[(size_t)r1g * K2DIM + u] = hw;
        g_aol[(size_t)r1g * K2DIM + u] = lw;
    }
}

// ---------------- launch ---------------------------------------------------------
extern "C" void kernel_launch(void* const* d_in, const int* in_sizes, int n_in,
                              void* d_out, int out_size) {
    (void)in_sizes; (void)n_in; (void)out_size;
    const float* x        = (const float*)d_in[0];
    const float* pos_bias = (const float*)d_in[1];
    const float* gamma    = (const float*)d_in[2];
    const float* wq       = (const float*)d_in[3];
    const float* wk       = (const float*)d_in[4];
    const float* wv       = (const float*)d_in[5];
    const float* wo       = (const float*)d_in[6];
    float* out = (float*)d_out;

    unsigned *xnh_p, *xnl_p, *wch_p, *wcl_p, *woh_p, *wol_p, *aoh_p, *aol_p;
    cudaGetSymbolAddress((void**)&xnh_p, g_xnh);
    cudaGetSymbolAddress((void**)&xnl_p, g_xnl);
    cudaGetSymbolAddress((void**)&wch_p, g_wch);
    cudaGetSymbolAddress((void**)&wcl_p, g_wcl);
    cudaGetSymbolAddress((void**)&woh_p, g_woh);
    cudaGetSymbolAddress((void**)&wol_p, g_wol);
    cudaGetSymbolAddress((void**)&aoh_p, g_aoh);
    cudaGetSymbolAddress((void**)&aol_p, g_aol);

    const int GEMM_SMEM = 2 * 8192 * 4;      // 65536
    const int ATTN_SMEM = 22784 * 4;         // 91136
    cudaFuncSetAttribute(gemm_h2_kernel<0>, cudaFuncAttributeMaxDynamicSharedMemorySize, GEMM_SMEM);
    cudaFuncSetAttribute(gemm_h2_kernel<1>, cudaFuncAttributeMaxDynamicSharedMemorySize, GEMM_SMEM);
    cudaFuncSetAttribute(attn_mma_kernel, cudaFuncAttributeMaxDynamicSharedMemorySize, ATTN_SMEM);

    dim3 tb(32, 8);
    transpose_split_kernel<<<dim3(64, 64), tb>>>(wq, wch_p, wcl_p, DIMM, SCALEF);
    transpose_split_kernel<<<dim3(4, 64), tb>>>(wk, wch_p + (size_t)2048 * K2DIM,
                                                wcl_p + (size_t)2048 * K2DIM, DHEAD, 1.0f);
    transpose_split_kernel<<<dim3(4, 64), tb>>>(wv, wch_p + (size_t)2176 * K2DIM,
                                                wcl_p + (size_t)2176 * K2DIM, DHEAD, 1.0f);
    transpose_split_kernel<<<dim3(64, 64), tb>>>(wo, woh_p, wol_p, DIMM, 1.0f);

    rmsnorm_split_kernel<<<SEQ, 256>>>(x, gamma);

    gemm_h2_kernel<1><<<dim3(18, 16), 256, GEMM_SMEM>>>(
        xnh_p, xnl_p, wch_p, wcl_p, nullptr, QKVN);

    vprep_kernel<<<512, 256>>>();
    vpart_kernel<<<16, 128>>>();
    vsuf_kernel<<<16, 128>>>();

    attn_mma_kernel<<<dim3(32, HEADS), 256, ATTN_SMEM>>>(pos_bias);

    gemm_h2_kernel<0><<<dim3(16, 16), 256, GEMM_SMEM>>>(
        aoh_p, aol_p, woh_p, wol_p, out, DIMM);
}

// round 8
// speedup vs baseline: 1.0670x; 1.0670x over previous
#include <cuda_runtime.h>
#include <cuda_fp16.h>
#include <math.h>
#include <stddef.h>
#include <stdint.h>

#define SEQ    2048
#define DIMM   2048
#define HEADS  16
#define DHEAD  128
#define QKVN   2304
#define K2DIM  1024          // K/2 half2 units per row
#define EPSF   1e-5f
#define MASKVF 1e-10f
#define SCALEF 0.08838834764831845f

// ---------------- scratch (hi/lo interleaved as uint2 {h,l}) -----------------
__device__ uint2    g_xn2[SEQ * K2DIM];
__device__ uint2    g_wc2[QKVN * K2DIM];     // [wq|wk|wv]^T (q pre-scaled)
__device__ uint2    g_wo2[DIMM * K2DIM];
__device__ uint2    g_ao2[SEQ * K2DIM];
__device__ uint4    g_qh4[HEADS * 128 * 8 * 32];   // Q fragments hi
__device__ uint4    g_ql4[HEADS * 128 * 8 * 32];   // Q fragments lo
__device__ uint2    g_kt2[64 * SEQ];         // K^T half2-packed along d, {h,l}
__device__ float    g_v[SEQ * DHEAD];        // V dense fp32
__device__ uint2    g_vt2[(SEQ / 2) * DHEAD];
__device__ float    g_vsuf[SEQ * DHEAD];
__device__ float    g_vpart[16 * DHEAD];

// ---------------- helpers ----------------------------------------------------
__device__ __forceinline__ void cvt_h2(float x0, float x1, unsigned& h, unsigned& l) {
    __half2 hh = __floats2half2_rn(x0, x1);
    __half2 ll = __floats2half2_rn(x0 - __low2float(hh), x1 - __high2float(hh));
    h = *reinterpret_cast<unsigned*>(&hh);
    l = *reinterpret_cast<unsigned*>(&ll);
}
#define MMA_F16(Cacc, Av, Bv)                                               \
    asm volatile("mma.sync.aligned.m16n8k16.row.col.f32.f16.f16.f32 "       \
        "{%0,%1,%2,%3}, {%4,%5,%6,%7}, {%8,%9}, {%0,%1,%2,%3};"             \
        : "+f"((Cacc)[0]), "+f"((Cacc)[1]), "+f"((Cacc)[2]), "+f"((Cacc)[3])\
        : "r"((Av).x), "r"((Av).y), "r"((Av).z), "r"((Av).w),               \
          "r"((Bv).x), "r"((Bv).y))

// ---------------- RMSNorm -> interleaved half2 hi/lo --------------------------
__global__ void rmsnorm_split_kernel(const float* __restrict__ x,
                                     const float* __restrict__ gamma) {
    int row = blockIdx.x;
    const float* xr = x + (size_t)row * DIMM;
    float ss = 0.f;
    for (int i = threadIdx.x; i < DIMM; i += 256) { float v = xr[i]; ss += v * v; }
    __shared__ float red[8];
    #pragma unroll
    for (int o = 16; o; o >>= 1) ss += __shfl_xor_sync(0xffffffffu, ss, o);
    if ((threadIdx.x & 31) == 0) red[threadIdx.x >> 5] = ss;
    __syncthreads();
    if (threadIdx.x < 32) {
        float v = (threadIdx.x < 8) ? red[threadIdx.x] : 0.f;
        #pragma unroll
        for (int o = 4; o; o >>= 1) v += __shfl_xor_sync(0xffffffffu, v, o);
        if (threadIdx.x == 0) red[0] = v;
    }
    __syncthreads();
    float inv = rsqrtf(red[0] / (float)DIMM + EPSF);
    for (int u = threadIdx.x; u < K2DIM; u += 256) {
        float2 xv = *(const float2*)(xr + 2 * u);
        float2 gv = *(const float2*)(gamma + 2 * u);
        unsigned h, l;
        cvt_h2(xv.x * inv * gv.x, xv.y * inv * gv.y, h, l);
        g_xn2[(size_t)row * K2DIM + u] = make_uint2(h, l);
    }
}

// ---------------- transpose + split -> interleaved ----------------------------
__global__ void transpose_split_kernel(const float* __restrict__ src,
                                       uint2* __restrict__ dst,
                                       int C, float scale) {
    __shared__ float tile[32][33];
    int bx = blockIdx.x * 32, by = blockIdx.y * 32;   // bx: n, by: k
    int tx = threadIdx.x, ty = threadIdx.y;           // 32 x 8
    #pragma unroll
    for (int j = 0; j < 32; j += 8)
        tile[ty + j][tx] = src[(size_t)(by + ty + j) * C + bx + tx];
    __syncthreads();
    int ul = tx & 15, nb = ty * 2 + (tx >> 4);
    #pragma unroll
    for (int rep = 0; rep < 2; rep++) {
        int nl = nb + rep * 16;
        float v0 = tile[2 * ul][nl] * scale;
        float v1 = tile[2 * ul + 1][nl] * scale;
        unsigned h, l;
        cvt_h2(v0, v1, h, l);
        dst[(size_t)(bx + nl) * K2DIM + (by >> 1) + ul] = make_uint2(h, l);
    }
}

// ---------------- fp16x3 GEMM on interleaved half2 planes ---------------------
// 128x128 tile, 8 warps (4m x 2n), K-stage 32, double-buffered, pure-copy stage.
template <int EPI>
__global__ __launch_bounds__(256) void gemm_h2_kernel(
    const uint2* __restrict__ A2, const uint2* __restrict__ B2,
    float* __restrict__ C, int N)
{
    extern __shared__ unsigned smu[];
    const int tid = threadIdx.x, lane = tid & 31, warp = tid >> 5;
    const int m0 = blockIdx.y << 7, n0 = blockIdx.x << 7;
    const int wm = warp >> 1, wn = warp & 1;
    const int gid = lane >> 2, tig = lane & 3;

    float acc[2][8][4];
    #pragma unroll
    for (int mf = 0; mf < 2; mf++)
        #pragma unroll
        for (int nf = 0; nf < 8; nf++)
            #pragma unroll
            for (int q = 0; q < 4; q++) acc[mf][nf][q] = 0.f;

    uint2 ra2[2][4], rb2[4][2];
    const int arow = m0 + warp * 16 + gid;

    #pragma unroll
    for (int i = 0; i < 2; i++) {
        int u0 = 8 * i + tig;
        ra2[i][0] = A2[(size_t)arow * K2DIM + u0];
        ra2[i][1] = A2[(size_t)(arow + 8) * K2DIM + u0];
        ra2[i][2] = A2[(size_t)arow * K2DIM + u0 + 4];
        ra2[i][3] = A2[(size_t)(arow + 8) * K2DIM + u0 + 4];
    }
    #pragma unroll
    for (int j = 0; j < 4; j++) {
        int n = n0 + (warp + 8 * (j & 1)) * 8 + gid;
        int u0 = (j >> 1) * 8 + tig;
        rb2[j][0] = B2[(size_t)n * K2DIM + u0];
        rb2[j][1] = B2[(size_t)n * K2DIM + u0 + 4];
    }

    const int S = 64;   // 2048 / 32
    for (int s = 0; s < S; s++) {
        unsigned* buf = smu + (s & 1) * 8192;
        uint4* Ah4 = (uint4*)buf;
        uint4* Al4 = (uint4*)(buf + 2048);
        uint2* Bh2 = (uint2*)(buf + 4096);
        uint2* Bl2 = (uint2*)(buf + 6144);

        #pragma unroll
        for (int i = 0; i < 2; i++) {
            int slot = warp + 8 * i;
            Ah4[slot * 32 + lane] = make_uint4(ra2[i][0].x, ra2[i][1].x, ra2[i][2].x, ra2[i][3].x);
            Al4[slot * 32 + lane] = make_uint4(ra2[i][0].y, ra2[i][1].y, ra2[i][2].y, ra2[i][3].y);
        }
        #pragma unroll
        for (int j = 0; j < 4; j++) {
            int slot = (j >> 1) * 16 + warp + 8 * (j & 1);
            Bh2[slot * 32 + lane] = make_uint2(rb2[j][0].x, rb2[j][1].x);
            Bl2[slot * 32 + lane] = make_uint2(rb2[j][0].y, rb2[j][1].y);
        }
        __syncthreads();

        if (s + 1 < S) {
            const int ub = (s + 1) << 4;
            #pragma unroll
            for (int i = 0; i < 2; i++) {
                int u0 = ub + 8 * i + tig;
                ra2[i][0] = A2[(size_t)arow * K2DIM + u0];
                ra2[i][1] = A2[(size_t)(arow + 8) * K2DIM + u0];
                ra2[i][2] = A2[(size_t)arow * K2DIM + u0 + 4];
                ra2[i][3] = A2[(size_t)(arow + 8) * K2DIM + u0 + 4];
            }
            #pragma unroll
            for (int j = 0; j < 4; j++) {
                int n = n0 + (warp + 8 * (j & 1)) * 8 + gid;
                int u0 = ub + (j >> 1) * 8 + tig;
                rb2[j][0] = B2[(size_t)n * K2DIM + u0];
                rb2[j][1] = B2[(size_t)n * K2DIM + u0 + 4];
            }
        }

        #pragma unroll
        for (int kk = 0; kk < 2; kk++) {
            uint4 ah[2], al[2];
            uint2 bh[8], bl[8];
            #pragma unroll
            for (int mf = 0; mf < 2; mf++) {
                int slot = kk * 8 + wm * 2 + mf;
                ah[mf] = Ah4[slot * 32 + lane];
                al[mf] = Al4[slot * 32 + lane];
            }
            #pragma unroll
            for (int nf = 0; nf < 8; nf++) {
                int slot = kk * 16 + wn * 8 + nf;
                bh[nf] = Bh2[slot * 32 + lane];
                bl[nf] = Bl2[slot * 32 + lane];
            }
            // term-major ordering: consecutive MMAs hit different accumulators
            #pragma unroll
            for (int nf = 0; nf < 8; nf++)
                #pragma unroll
                for (int mf = 0; mf < 2; mf++)
                    MMA_F16(acc[mf][nf], ah[mf], bh[nf]);
            #pragma unroll
            for (int nf = 0; nf < 8; nf++)
                #pragma unroll
                for (int mf = 0; mf < 2; mf++)
                    MMA_F16(acc[mf][nf], ah[mf], bl[nf]);
            #pragma unroll
            for (int nf = 0; nf < 8; nf++)
                #pragma unroll
                for (int mf = 0; mf < 2; mf++)
                    MMA_F16(acc[mf][nf], al[mf], bh[nf]);
        }
        __syncthreads();
    }

    if (EPI == 0) {
        #pragma unroll
        for (int mf = 0; mf < 2; mf++) {
            const int r0 = m0 + wm * 32 + mf * 16 + gid;
            #pragma unroll
            for (int nf = 0; nf < 8; nf++) {
                const int c = n0 + wn * 64 + nf * 8 + tig * 2;
                *(float2*)(C + (size_t)r0 * N + c) = make_float2(acc[mf][nf][0], acc[mf][nf][1]);
                *(float2*)(C + (size_t)(r0 + 8) * N + c) = make_float2(acc[mf][nf][2], acc[mf][nf][3]);
            }
        }
    } else {
        const int bx = blockIdx.x;
        if (bx < 16) {
            // Q: write attention A-fragments directly (hi/lo)
            const int h = bx;
            #pragma unroll
            for (int mf = 0; mf < 2; mf++) {
                int rg = (m0 >> 4) + wm * 2 + mf;
                #pragma unroll
                for (int k2 = 0; k2 < 4; k2++) {
                    int kkg = wn * 4 + k2;
                    const float* e = acc[mf][2 * k2];
                    const float* o = acc[mf][2 * k2 + 1];
                    uint4 hv, lv;
                    cvt_h2(e[0], e[1], hv.x, lv.x);
                    cvt_h2(e[2], e[3], hv.y, lv.y);
                    cvt_h2(o[0], o[1], hv.z, lv.z);
                    cvt_h2(o[2], o[3], hv.w, lv.w);
                    size_t idx = ((size_t)(h * 128 + rg) * 8 + kkg) * 32 + lane;
                    g_qh4[idx] = hv;
                    g_ql4[idx] = lv;
                }
            }
        } else if (bx == 16) {
            // K: transposed interleaved half2 planes
            #pragma unroll
            for (int mf = 0; mf < 2; mf++) {
                int j = m0 + wm * 32 + mf * 16 + gid;
                #pragma unroll
                for (int nf = 0; nf < 8; nf++) {
                    int d2 = wn * 32 + nf * 4 + tig;
                    unsigned h0, l0, h1, l1;
                    cvt_h2(acc[mf][nf][0], acc[mf][nf][1], h0, l0);
                    cvt_h2(acc[mf][nf][2], acc[mf][nf][3], h1, l1);
                    g_kt2[d2 * SEQ + j]     = make_uint2(h0, l0);
                    g_kt2[d2 * SEQ + j + 8] = make_uint2(h1, l1);
                }
            }
        } else {
            // V: dense fp32
            #pragma unroll
            for (int mf = 0; mf < 2; mf++) {
                int j = m0 + wm * 32 + mf * 16 + gid;
                #pragma unroll
                for (int nf = 0; nf < 8; nf++) {
                    int d = wn * 64 + nf * 8 + tig * 2;
                    *(float2*)&g_v[(size_t)j * DHEAD + d] =
                        make_float2(acc[mf][nf][0], acc[mf][nf][1]);
                    *(float2*)&g_v[(size_t)(j + 8) * DHEAD + d] =
                        make_float2(acc[mf][nf][2], acc[mf][nf][3]);
                }
            }
        }
    }
}

// ---------------- V j-paired interleaved half2 planes --------------------------
__global__ void vprep_kernel() {
    int t = blockIdx.x * 256 + threadIdx.x;     // 131072
    int d = t & 127, j2 = t >> 7;
    float v0 = g_v[(size_t)(2 * j2) * DHEAD + d];
    float v1 = g_v[(size_t)(2 * j2 + 1) * DHEAD + d];
    unsigned h, l;
    cvt_h2(v0, v1, h, l);
    g_vt2[j2 * DHEAD + d] = make_uint2(h, l);
}

// ---------------- V suffix sums ------------------------------------------------
__global__ void vpart_kernel() {
    int blk = blockIdx.x, d = threadIdx.x;
    float s = 0.f;
    #pragma unroll 8
    for (int r = 0; r < 128; r++)
        s += g_v[(size_t)(blk * 128 + r) * DHEAD + d];
    g_vpart[blk * DHEAD + d] = s;
}
__global__ void vsuf_kernel() {
    int blk = blockIdx.x, d = threadIdx.x;
    float acc = 0.f;
    for (int b = blk + 1; b < 16; b++) acc += g_vpart[b * DHEAD + d];
    #pragma unroll 4
    for (int r = 127; r >= 0; r--) {
        int row = blk * 128 + r;
        g_vsuf[(size_t)row * DHEAD + d] = acc;
        acc += g_v[(size_t)row * DHEAD + d];
    }
}

// ---------------- fp16x3 tensor-core flash attention ----------------------------
// smem uint2 layout: Kint[64][68]@0 (4352), Vint[32][132]@4352 (4224),
// Pint[64][36]@8576 (2304) -> 10880 uint2 = 21760 floats;
// then srmax @21760 (128 floats), srsum @21888 (128 floats) -> 22016 floats total.
__global__ __launch_bounds__(256) void attn_mma_kernel(const float* __restrict__ pos_bias) {
    extern __shared__ float sm[];
    uint2* Kint = (uint2*)sm;
    uint2* Vint = (uint2*)sm + 4352;
    uint2* Pint = (uint2*)sm + 8576;
    float* srmax = sm + 21760;
    float* srsum = sm + 21888;

    const int h  = blockIdx.y;
    const int ib = gridDim.x - 1 - blockIdx.x;
    const int i0 = ib * 64;
    const int tid = threadIdx.x, lane = tid & 31, warp = tid >> 5;
    const int wm = warp >> 1, wn = warp & 1;
    const int gid = lane >> 2, tig = lane & 3;

    const int rg = (i0 >> 4) + wm;
    const size_t qbase = ((size_t)(h * 128 + rg) * 8) * 32 + lane;

    const int jl = tid & 63, cb = tid >> 6;
    const int r0g = i0 + wm * 16 + gid, r1g = r0g + 8;
    const int rl0 = wm * 16 + gid;

    float o[8][4];
    #pragma unroll
    for (int nf = 0; nf < 8; nf++)
        #pragma unroll
        for (int q = 0; q < 4; q++) o[nf][q] = 0.f;
    float m0 = -1e30f, m1 = -1e30f, l0 = 0.f, l1 = 0.f;

    for (int jb = 0; jb <= ib; jb++) {
        const int j0 = jb * 64;
        __syncthreads();
        #pragma unroll
        for (int it = 0; it < 16; it++) {
            int d2 = cb * 16 + it;
            Kint[d2 * 68 + jl] = g_kt2[d2 * SEQ + j0 + jl];
        }
        #pragma unroll
        for (int it = 0; it < 16; it++) {
            int idx = it * 256 + tid;
            int j2 = idx >> 7, d = idx & 127;
            Vint[j2 * 132 + d] = g_vt2[(j0 / 2 + j2) * DHEAD + d];
        }
        __syncthreads();

        // ---- S = Q K^T (fp16 x3)
        float s[4][4];
        #pragma unroll
        for (int nf = 0; nf < 4; nf++)
            #pragma unroll
            for (int q = 0; q < 4; q++) s[nf][q] = 0.f;

        #pragma unroll
        for (int kk = 0; kk < 8; kk++) {
            uint4 qh = g_qh4[qbase + kk * 32];
            uint4 ql = g_ql4[qbase + kk * 32];
            const int kr0 = (kk * 8 + tig) * 68, kr1 = kr0 + 4 * 68;
            uint2 bh[4], bl[4];
            #pragma unroll
            for (int nf = 0; nf < 4; nf++) {
                int col = wn * 32 + nf * 8 + gid;
                uint2 kv0 = Kint[kr0 + col];
                uint2 kv1 = Kint[kr1 + col];
                bh[nf] = make_uint2(kv0.x, kv1.x);
                bl[nf] = make_uint2(kv0.y, kv1.y);
            }
            #pragma unroll
            for (int nf = 0; nf < 4; nf++) MMA_F16(s[nf], qh, bh[nf]);
            #pragma unroll
            for (int nf = 0; nf < 4; nf++) MMA_F16(s[nf], qh, bl[nf]);
            #pragma unroll
            for (int nf = 0; nf < 4; nf++) MMA_F16(s[nf], ql, bh[nf]);
        }

        const float* pb0 = pos_bias + ((size_t)h * SEQ + r0g) * SEQ + j0 + wn * 32 + tig * 2;
        const float* pb1 = pb0 + (size_t)8 * SEQ;
        #pragma unroll
        for (int nf = 0; nf < 4; nf++) {
            float2 b0 = *(const float2*)(pb0 + nf * 8);
            float2 b1 = *(const float2*)(pb1 + nf * 8);
            s[nf][0] += b0.x; s[nf][1] += b0.y;
            s[nf][2] += b1.x; s[nf][3] += b1.y;
        }
        if (jb == ib) {
            #pragma unroll
            for (int nf = 0; nf < 4; nf++) {
                int c = j0 + wn * 32 + nf * 8 + tig * 2;
                if (c > r0g)     s[nf][0] = -1e30f;
                if (c + 1 > r0g) s[nf][1] = -1e30f;
                if (c > r1g)     s[nf][2] = -1e30f;
                if (c + 1 > r1g) s[nf][3] = -1e30f;
            }
        }

        float rm0 = -1e30f, rm1 = -1e30f;
        #pragma unroll
        for (int nf = 0; nf < 4; nf++) {
            rm0 = fmaxf(rm0, fmaxf(s[nf][0], s[nf][1]));
            rm1 = fmaxf(rm1, fmaxf(s[nf][2], s[nf][3]));
        }
        rm0 = fmaxf(rm0, __shfl_xor_sync(0xffffffffu, rm0, 1));
        rm0 = fmaxf(rm0, __shfl_xor_sync(0xffffffffu, rm0, 2));
        rm1 = fmaxf(rm1, __shfl_xor_sync(0xffffffffu, rm1, 1));
        rm1 = fmaxf(rm1, __shfl_xor_sync(0xffffffffu, rm1, 2));
        srmax[wn * 64 + rl0] = rm0;
        srmax[wn * 64 + rl0 + 8] = rm1;
        __syncthreads();
        float bm0 = fmaxf(srmax[rl0], srmax[64 + rl0]);
        float bm1 = fmaxf(srmax[rl0 + 8], srmax[64 + rl0 + 8]);
        float mn0 = fmaxf(m0, bm0), mn1 = fmaxf(m1, bm1);
        float sc0 = __expf(m0 - mn0), sc1 = __expf(m1 - mn1);

        float rs0 = 0.f, rs1 = 0.f;
        #pragma unroll
        for (int nf = 0; nf < 4; nf++) {
            int pcol = wn * 16 + nf * 4 + tig;
            float p00 = __expf(s[nf][0] - mn0);
            float p01 = __expf(s[nf][1] - mn0);
            float p10 = __expf(s[nf][2] - mn1);
            float p11 = __expf(s[nf][3] - mn1);
            rs0 += p00 + p01; rs1 += p10 + p11;
            unsigned hw, lw;
            cvt_h2(p00, p01, hw, lw);
            Pint[rl0 * 36 + pcol] = make_uint2(hw, lw);
            cvt_h2(p10, p11, hw, lw);
            Pint[(rl0 + 8) * 36 + pcol] = make_uint2(hw, lw);
        }
        rs0 += __shfl_xor_sync(0xffffffffu, rs0, 1);
        rs0 += __shfl_xor_sync(0xffffffffu, rs0, 2);
        rs1 += __shfl_xor_sync(0xffffffffu, rs1, 1);
        rs1 += __shfl_xor_sync(0xffffffffu, rs1, 2);
        srsum[wn * 64 + rl0] = rs0;
        srsum[wn * 64 + rl0 + 8] = rs1;
        __syncthreads();
        l0 = l0 * sc0 + srsum[rl0] + srsum[64 + rl0];
        l1 = l1 * sc1 + srsum[rl0 + 8] + srsum[64 + rl0 + 8];
        m0 = mn0; m1 = mn1;

        #pragma unroll
        for (int nf = 0; nf < 8; nf++) {
            o[nf][0] *= sc0; o[nf][1] *= sc0;
            o[nf][2] *= sc1; o[nf][3] *= sc1;
        }
        #pragma unroll
        for (int c = 0; c < 4; c++) {
            uint2 p0 = Pint[rl0 * 36 + c * 8 + tig];
            uint2 p1 = Pint[(rl0 + 8) * 36 + c * 8 + tig];
            uint2 p2 = Pint[rl0 * 36 + c * 8 + 4 + tig];
            uint2 p3 = Pint[(rl0 + 8) * 36 + c * 8 + 4 + tig];
            uint4 ah = make_uint4(p0.x, p1.x, p2.x, p3.x);
            uint4 al = make_uint4(p0.y, p1.y, p2.y, p3.y);
            const int vr0 = (c * 8 + tig) * 132, vr1 = vr0 + 4 * 132;
            #pragma unroll
            for (int nf = 0; nf < 8; nf++) {
                int dcol = wn * 64 + nf * 8 + gid;
                uint2 vv0 = Vint[vr0 + dcol];
                uint2 vv1 = Vint[vr1 + dcol];
                uint2 bh = make_uint2(vv0.x, vv1.x);
                uint2 bl = make_uint2(vv0.y, vv1.y);
                MMA_F16(o[nf], ah, bh);
                MMA_F16(o[nf], ah, bl);
                MMA_F16(o[nf], al, bh);
            }
        }
    }

    // finalize + write interleaved ao planes
    float cnt0 = (float)(SEQ - 1 - r0g), cnt1 = (float)(SEQ - 1 - r1g);
    float mf0 = fmaxf(m0, MASKVF), mf1 = fmaxf(m1, MASKVF);
    float wu0 = __expf(m0 - mf0),  wu1 = __expf(m1 - mf1);
    float wk0 = __expf(MASKVF - mf0), wk1 = __expf(MASKVF - mf1);
    float iZ0 = 1.f / (l0 * wu0 + cnt0 * wk0);
    float iZ1 = 1.f / (l1 * wu1 + cnt1 * wk1);
    #pragma unroll
    for (int nf = 0; nf < 8; nf++) {
        int dcol = wn * 64 + nf * 8 + tig * 2;
        float2 vs0 = *(const float2*)&g_vsuf[(size_t)r0g * DHEAD + dcol];
        float2 vs1 = *(const float2*)&g_vsuf[(size_t)r1g * DHEAD + dcol];
        float o00 = (o[nf][0] * wu0 + wk0 * vs0.x) * iZ0;
        float o01 = (o[nf][1] * wu0 + wk0 * vs0.y) * iZ0;
        float o10 = (o[nf][2] * wu1 + wk1 * vs1.x) * iZ1;
        float o11 = (o[nf][3] * wu1 + wk1 * vs1.y) * iZ1;
        unsigned hw, lw;
        size_t u = (size_t)(h * DHEAD + dcol) >> 1;
        cvt_h2(o00, o01, hw, lw);
        g_ao2[(size_t)r0g * K2DIM + u] = make_uint2(hw, lw);
        cvt_h2(o10, o11, hw, lw);
        g_ao2[(size_t)r1g * K2DIM + u] = make_uint2(hw, lw);
    }
}

// ---------------- launch ---------------------------------------------------------
extern "C" void kernel_launch(void* const* d_in, const int* in_sizes, int n_in,
                              void* d_out, int out_size) {
    (void)in_sizes; (void)n_in; (void)out_size;
    const float* x        = (const float*)d_in[0];
    const float* pos_bias = (const float*)d_in[1];
    const float* gamma    = (const float*)d_in[2];
    const float* wq       = (const float*)d_in[3];
    const float* wk       = (const float*)d_in[4];
    const float* wv       = (const float*)d_in[5];
    const float* wo       = (const float*)d_in[6];
    float* out = (float*)d_out;

    uint2 *xn2_p, *wc2_p, *wo2_p, *ao2_p;
    cudaGetSymbolAddress((void**)&xn2_p, g_xn2);
    cudaGetSymbolAddress((void**)&wc2_p, g_wc2);
    cudaGetSymbolAddress((void**)&wo2_p, g_wo2);
    cudaGetSymbolAddress((void**)&ao2_p, g_ao2);

    const int GEMM_SMEM = 2 * 8192 * 4;      // 65536
    const int ATTN_SMEM = 22016 * 4;         // 88064 (21760 data + 2*128 reduce)
    cudaFuncSetAttribute(gemm_h2_kernel<0>, cudaFuncAttributeMaxDynamicSharedMemorySize, GEMM_SMEM);
    cudaFuncSetAttribute(gemm_h2_kernel<1>, cudaFuncAttributeMaxDynamicSharedMemorySize, GEMM_SMEM);
    cudaFuncSetAttribute(attn_mma_kernel, cudaFuncAttributeMaxDynamicSharedMemorySize, ATTN_SMEM);

    dim3 tb(32, 8);
    transpose_split_kernel<<<dim3(64, 64), tb>>>(wq, wc2_p, DIMM, SCALEF);
    transpose_split_kernel<<<dim3(4, 64), tb>>>(wk, wc2_p + (size_t)2048 * K2DIM, DHEAD, 1.0f);
    transpose_split_kernel<<<dim3(4, 64), tb>>>(wv, wc2_p + (size_t)2176 * K2DIM, DHEAD, 1.0f);
    transpose_split_kernel<<<dim3(64, 64), tb>>>(wo, wo2_p, DIMM, 1.0f);

    rmsnorm_split_kernel<<<SEQ, 256>>>(x, gamma);

    gemm_h2_kernel<1><<<dim3(18, 16), 256, GEMM_SMEM>>>(xn2_p, wc2_p, nullptr, QKVN);

    vprep_kernel<<<512, 256>>>();
    vpart_kernel<<<16, 128>>>();
    vsuf_kernel<<<16, 128>>>();

    attn_mma_kernel<<<dim3(32, HEADS), 256, ATTN_SMEM>>>(pos_bias);

    gemm_h2_kernel<0><<<dim3(16, 16), 256, GEMM_SMEM>>>(ao2_p, wo2_p, out, DIMM);
}

// round 9
// speedup vs baseline: 1.1209x; 1.0505x over previous
#include <cuda_runtime.h>
#include <cuda_fp16.h>
#include <math.h>
#include <stddef.h>
#include <stdint.h>

#define SEQ    2048
#define DIMM   2048
#define HEADS  16
#define DHEAD  128
#define QKVN   2304
#define K2DIM  1024          // K/2 half2 units per row
#define EPSF   1e-5f
#define MASKVF 1e-10f
#define SCALEF 0.08838834764831845f

// ---------------- scratch (hi/lo interleaved as uint2 {h,l}) -----------------
__device__ uint2    g_xn2[SEQ * K2DIM];
__device__ uint2    g_wc2[QKVN * K2DIM];     // [wq|wk|wv]^T (q pre-scaled)
__device__ uint2    g_wo2[DIMM * K2DIM];
__device__ uint2    g_ao2[SEQ * K2DIM];
__device__ uint4    g_qh4[HEADS * 128 * 8 * 32];   // Q fragments hi
__device__ uint4    g_ql4[HEADS * 128 * 8 * 32];   // Q fragments lo
__device__ uint2    g_kt2[64 * SEQ];         // K^T half2-packed along d, {h,l}
__device__ float    g_v[SEQ * DHEAD];        // V dense fp32
__device__ uint2    g_vt2[(SEQ / 2) * DHEAD];
__device__ float    g_vsuf[SEQ * DHEAD];
__device__ float    g_vpart[16 * DHEAD];

// ---------------- helpers ----------------------------------------------------
__device__ __forceinline__ void cvt_h2(float x0, float x1, unsigned& h, unsigned& l) {
    __half2 hh = __floats2half2_rn(x0, x1);
    __half2 ll = __floats2half2_rn(x0 - __low2float(hh), x1 - __high2float(hh));
    h = *reinterpret_cast<unsigned*>(&hh);
    l = *reinterpret_cast<unsigned*>(&ll);
}
#define MMA_F16(Cacc, Av, Bv)                                               \
    asm volatile("mma.sync.aligned.m16n8k16.row.col.f32.f16.f16.f32 "       \
        "{%0,%1,%2,%3}, {%4,%5,%6,%7}, {%8,%9}, {%0,%1,%2,%3};"             \
        : "+f"((Cacc)[0]), "+f"((Cacc)[1]), "+f"((Cacc)[2]), "+f"((Cacc)[3])\
        : "r"((Av).x), "r"((Av).y), "r"((Av).z), "r"((Av).w),               \
          "r"((Bv).x), "r"((Bv).y))

// ---------------- RMSNorm -> interleaved half2 hi/lo --------------------------
__global__ void rmsnorm_split_kernel(const float* __restrict__ x,
                                     const float* __restrict__ gamma) {
    int row = blockIdx.x;
    const float* xr = x + (size_t)row * DIMM;
    float ss = 0.f;
    for (int i = threadIdx.x; i < DIMM; i += 256) { float v = xr[i]; ss += v * v; }
    __shared__ float red[8];
    #pragma unroll
    for (int o = 16; o; o >>= 1) ss += __shfl_xor_sync(0xffffffffu, ss, o);
    if ((threadIdx.x & 31) == 0) red[threadIdx.x >> 5] = ss;
    __syncthreads();
    if (threadIdx.x < 32) {
        float v = (threadIdx.x < 8) ? red[threadIdx.x] : 0.f;
        #pragma unroll
        for (int o = 4; o; o >>= 1) v += __shfl_xor_sync(0xffffffffu, v, o);
        if (threadIdx.x == 0) red[0] = v;
    }
    __syncthreads();
    float inv = rsqrtf(red[0] / (float)DIMM + EPSF);
    for (int u = threadIdx.x; u < K2DIM; u += 256) {
        float2 xv = *(const float2*)(xr + 2 * u);
        float2 gv = *(const float2*)(gamma + 2 * u);
        unsigned h, l;
        cvt_h2(xv.x * inv * gv.x, xv.y * inv * gv.y, h, l);
        g_xn2[(size_t)row * K2DIM + u] = make_uint2(h, l);
    }
}

// ---------------- transpose + split -> interleaved ----------------------------
__global__ void transpose_split_kernel(const float* __restrict__ src,
                                       uint2* __restrict__ dst,
                                       int C, float scale) {
    __shared__ float tile[32][33];
    int bx = blockIdx.x * 32, by = blockIdx.y * 32;   // bx: n, by: k
    int tx = threadIdx.x, ty = threadIdx.y;           // 32 x 8
    #pragma unroll
    for (int j = 0; j < 32; j += 8)
        tile[ty + j][tx] = src[(size_t)(by + ty + j) * C + bx + tx];
    __syncthreads();
    int ul = tx & 15, nb = ty * 2 + (tx >> 4);
    #pragma unroll
    for (int rep = 0; rep < 2; rep++) {
        int nl = nb + rep * 16;
        float v0 = tile[2 * ul][nl] * scale;
        float v1 = tile[2 * ul + 1][nl] * scale;
        unsigned h, l;
        cvt_h2(v0, v1, h, l);
        dst[(size_t)(bx + nl) * K2DIM + (by >> 1) + ul] = make_uint2(h, l);
    }
}

// ---------------- fp16 split GEMM on interleaved half2 planes -----------------
// 128x128 tile, 8 warps (4m x 2n), K-stage 32, double-buffered, pure-copy stage.
// EPI=0: write fp32 C.  EPI=1: QKV epilogue.  TERMS: 3 = full x3, 2 = drop Al*Bh.
template <int EPI, int TERMS>
__global__ __launch_bounds__(256) void gemm_h2_kernel(
    const uint2* __restrict__ A2, const uint2* __restrict__ B2,
    float* __restrict__ C, int N)
{
    extern __shared__ unsigned smu[];
    const int tid = threadIdx.x, lane = tid & 31, warp = tid >> 5;
    const int m0 = blockIdx.y << 7, n0 = blockIdx.x << 7;
    const int wm = warp >> 1, wn = warp & 1;
    const int gid = lane >> 2, tig = lane & 3;

    float acc[2][8][4];
    #pragma unroll
    for (int mf = 0; mf < 2; mf++)
        #pragma unroll
        for (int nf = 0; nf < 8; nf++)
            #pragma unroll
            for (int q = 0; q < 4; q++) acc[mf][nf][q] = 0.f;

    uint2 ra2[2][4], rb2[4][2];
    const int arow = m0 + warp * 16 + gid;

    #pragma unroll
    for (int i = 0; i < 2; i++) {
        int u0 = 8 * i + tig;
        ra2[i][0] = A2[(size_t)arow * K2DIM + u0];
        ra2[i][1] = A2[(size_t)(arow + 8) * K2DIM + u0];
        ra2[i][2] = A2[(size_t)arow * K2DIM + u0 + 4];
        ra2[i][3] = A2[(size_t)(arow + 8) * K2DIM + u0 + 4];
    }
    #pragma unroll
    for (int j = 0; j < 4; j++) {
        int n = n0 + (warp + 8 * (j & 1)) * 8 + gid;
        int u0 = (j >> 1) * 8 + tig;
        rb2[j][0] = B2[(size_t)n * K2DIM + u0];
        rb2[j][1] = B2[(size_t)n * K2DIM + u0 + 4];
    }

    const int S = 64;   // 2048 / 32
    for (int s = 0; s < S; s++) {
        unsigned* buf = smu + (s & 1) * 8192;
        uint4* Ah4 = (uint4*)buf;
        uint4* Al4 = (uint4*)(buf + 2048);
        uint2* Bh2 = (uint2*)(buf + 4096);
        uint2* Bl2 = (uint2*)(buf + 6144);

        #pragma unroll
        for (int i = 0; i < 2; i++) {
            int slot = warp + 8 * i;
            Ah4[slot * 32 + lane] = make_uint4(ra2[i][0].x, ra2[i][1].x, ra2[i][2].x, ra2[i][3].x);
            Al4[slot * 32 + lane] = make_uint4(ra2[i][0].y, ra2[i][1].y, ra2[i][2].y, ra2[i][3].y);
        }
        #pragma unroll
        for (int j = 0; j < 4; j++) {
            int slot = (j >> 1) * 16 + warp + 8 * (j & 1);
            Bh2[slot * 32 + lane] = make_uint2(rb2[j][0].x, rb2[j][1].x);
            Bl2[slot * 32 + lane] = make_uint2(rb2[j][0].y, rb2[j][1].y);
        }
        __syncthreads();

        if (s + 1 < S) {
            const int ub = (s + 1) << 4;
            #pragma unroll
            for (int i = 0; i < 2; i++) {
                int u0 = ub + 8 * i + tig;
                ra2[i][0] = A2[(size_t)arow * K2DIM + u0];
                ra2[i][1] = A2[(size_t)(arow + 8) * K2DIM + u0];
                ra2[i][2] = A2[(size_t)arow * K2DIM + u0 + 4];
                ra2[i][3] = A2[(size_t)(arow + 8) * K2DIM + u0 + 4];
            }
            #pragma unroll
            for (int j = 0; j < 4; j++) {
                int n = n0 + (warp + 8 * (j & 1)) * 8 + gid;
                int u0 = ub + (j >> 1) * 8 + tig;
                rb2[j][0] = B2[(size_t)n * K2DIM + u0];
                rb2[j][1] = B2[(size_t)n * K2DIM + u0 + 4];
            }
        }

        #pragma unroll
        for (int kk = 0; kk < 2; kk++) {
            uint4 ah[2], al[2];
            uint2 bh[8], bl[8];
            #pragma unroll
            for (int mf = 0; mf < 2; mf++) {
                int slot = kk * 8 + wm * 2 + mf;
                ah[mf] = Ah4[slot * 32 + lane];
                al[mf] = Al4[slot * 32 + lane];
            }
            #pragma unroll
            for (int nf = 0; nf < 8; nf++) {
                int slot = kk * 16 + wn * 8 + nf;
                bh[nf] = Bh2[slot * 32 + lane];
                bl[nf] = Bl2[slot * 32 + lane];
            }
            // term-major ordering: consecutive MMAs hit different accumulators
            #pragma unroll
            for (int nf = 0; nf < 8; nf++)
                #pragma unroll
                for (int mf = 0; mf < 2; mf++)
                    MMA_F16(acc[mf][nf], ah[mf], bh[nf]);
            #pragma unroll
            for (int nf = 0; nf < 8; nf++)
                #pragma unroll
                for (int mf = 0; mf < 2; mf++)
                    MMA_F16(acc[mf][nf], ah[mf], bl[nf]);
            if (TERMS == 3) {
                #pragma unroll
                for (int nf = 0; nf < 8; nf++)
                    #pragma unroll
                    for (int mf = 0; mf < 2; mf++)
                        MMA_F16(acc[mf][nf], al[mf], bh[nf]);
            }
        }
        __syncthreads();
    }

    if (EPI == 0) {
        #pragma unroll
        for (int mf = 0; mf < 2; mf++) {
            const int r0 = m0 + wm * 32 + mf * 16 + gid;
            #pragma unroll
            for (int nf = 0; nf < 8; nf++) {
                const int c = n0 + wn * 64 + nf * 8 + tig * 2;
                *(float2*)(C + (size_t)r0 * N + c) = make_float2(acc[mf][nf][0], acc[mf][nf][1]);
                *(float2*)(C + (size_t)(r0 + 8) * N + c) = make_float2(acc[mf][nf][2], acc[mf][nf][3]);
            }
        }
    } else {
        const int bx = blockIdx.x;
        if (bx < 16) {
            // Q: write attention A-fragments directly (hi/lo)
            const int h = bx;
            #pragma unroll
            for (int mf = 0; mf < 2; mf++) {
                int rg = (m0 >> 4) + wm * 2 + mf;
                #pragma unroll
                for (int k2 = 0; k2 < 4; k2++) {
                    int kkg = wn * 4 + k2;
                    const float* e = acc[mf][2 * k2];
                    const float* o = acc[mf][2 * k2 + 1];
                    uint4 hv, lv;
                    cvt_h2(e[0], e[1], hv.x, lv.x);
                    cvt_h2(e[2], e[3], hv.y, lv.y);
                    cvt_h2(o[0], o[1], hv.z, lv.z);
                    cvt_h2(o[2], o[3], hv.w, lv.w);
                    size_t idx = ((size_t)(h * 128 + rg) * 8 + kkg) * 32 + lane;
                    g_qh4[idx] = hv;
                    g_ql4[idx] = lv;
                }
            }
        } else if (bx == 16) {
            // K: transposed interleaved half2 planes
            #pragma unroll
            for (int mf = 0; mf < 2; mf++) {
                int j = m0 + wm * 32 + mf * 16 + gid;
                #pragma unroll
                for (int nf = 0; nf < 8; nf++) {
                    int d2 = wn * 32 + nf * 4 + tig;
                    unsigned h0, l0, h1, l1;
                    cvt_h2(acc[mf][nf][0], acc[mf][nf][1], h0, l0);
                    cvt_h2(acc[mf][nf][2], acc[mf][nf][3], h1, l1);
                    g_kt2[d2 * SEQ + j]     = make_uint2(h0, l0);
                    g_kt2[d2 * SEQ + j + 8] = make_uint2(h1, l1);
                }
            }
        } else {
            // V: dense fp32
            #pragma unroll
            for (int mf = 0; mf < 2; mf++) {
                int j = m0 + wm * 32 + mf * 16 + gid;
                #pragma unroll
                for (int nf = 0; nf < 8; nf++) {
                    int d = wn * 64 + nf * 8 + tig * 2;
                    *(float2*)&g_v[(size_t)j * DHEAD + d] =
                        make_float2(acc[mf][nf][0], acc[mf][nf][1]);
                    *(float2*)&g_v[(size_t)(j + 8) * DHEAD + d] =
                        make_float2(acc[mf][nf][2], acc[mf][nf][3]);
                }
            }
        }
    }
}

// ---------------- V j-paired interleaved half2 planes --------------------------
__global__ void vprep_kernel() {
    int t = blockIdx.x * 256 + threadIdx.x;     // 131072
    int d = t & 127, j2 = t >> 7;
    float v0 = g_v[(size_t)(2 * j2) * DHEAD + d];
    float v1 = g_v[(size_t)(2 * j2 + 1) * DHEAD + d];
    unsigned h, l;
    cvt_h2(v0, v1, h, l);
    g_vt2[j2 * DHEAD + d] = make_uint2(h, l);
}

// ---------------- V suffix sums ------------------------------------------------
__global__ void vpart_kernel() {
    int blk = blockIdx.x, d = threadIdx.x;
    float s = 0.f;
    #pragma unroll 8
    for (int r = 0; r < 128; r++)
        s += g_v[(size_t)(blk * 128 + r) * DHEAD + d];
    g_vpart[blk * DHEAD + d] = s;
}
__global__ void vsuf_kernel() {
    int blk = blockIdx.x, d = threadIdx.x;
    float acc = 0.f;
    for (int b = blk + 1; b < 16; b++) acc += g_vpart[b * DHEAD + d];
    #pragma unroll 4
    for (int r = 127; r >= 0; r--) {
        int row = blk * 128 + r;
        g_vsuf[(size_t)row * DHEAD + d] = acc;
        acc += g_v[(size_t)row * DHEAD + d];
    }
}

// ---------------- fp16 split tensor-core flash attention ------------------------
// QK^T: full x3.  PV: 2 terms (P_hi*V_hi + P_lo*V_hi); V_lo term dropped.
// smem uint2: Kint[64][68]@0, Vint[32][132]@4352, Pint[64][36]@8576 -> 21760 f,
// srmax @21760 (128 f), srsum @21888 (128 f) -> 22016 floats total.
__global__ __launch_bounds__(256) void attn_mma_kernel(const float* __restrict__ pos_bias) {
    extern __shared__ float sm[];
    uint2* Kint = (uint2*)sm;
    uint2* Vint = (uint2*)sm + 4352;
    uint2* Pint = (uint2*)sm + 8576;
    float* srmax = sm + 21760;
    float* srsum = sm + 21888;

    const int h  = blockIdx.y;
    const int ib = gridDim.x - 1 - blockIdx.x;
    const int i0 = ib * 64;
    const int tid = threadIdx.x, lane = tid & 31, warp = tid >> 5;
    const int wm = warp >> 1, wn = warp & 1;
    const int gid = lane >> 2, tig = lane & 3;

    const int rg = (i0 >> 4) + wm;
    const size_t qbase = ((size_t)(h * 128 + rg) * 8) * 32 + lane;

    const int jl = tid & 63, cb = tid >> 6;
    const int r0g = i0 + wm * 16 + gid, r1g = r0g + 8;
    const int rl0 = wm * 16 + gid;

    float o[8][4];
    #pragma unroll
    for (int nf = 0; nf < 8; nf++)
        #pragma unroll
        for (int q = 0; q < 4; q++) o[nf][q] = 0.f;
    float m0 = -1e30f, m1 = -1e30f, l0 = 0.f, l1 = 0.f;

    for (int jb = 0; jb <= ib; jb++) {
        const int j0 = jb * 64;
        __syncthreads();
        #pragma unroll
        for (int it = 0; it < 16; it++) {
            int d2 = cb * 16 + it;
            Kint[d2 * 68 + jl] = g_kt2[d2 * SEQ + j0 + jl];
        }
        #pragma unroll
        for (int it = 0; it < 16; it++) {
            int idx = it * 256 + tid;
            int j2 = idx >> 7, d = idx & 127;
            Vint[j2 * 132 + d] = g_vt2[(j0 / 2 + j2) * DHEAD + d];
        }
        __syncthreads();

        // ---- S = Q K^T (fp16 x3)
        float s[4][4];
        #pragma unroll
        for (int nf = 0; nf < 4; nf++)
            #pragma unroll
            for (int q = 0; q < 4; q++) s[nf][q] = 0.f;

        #pragma unroll
        for (int kk = 0; kk < 8; kk++) {
            uint4 qh = g_qh4[qbase + kk * 32];
            uint4 ql = g_ql4[qbase + kk * 32];
            const int kr0 = (kk * 8 + tig) * 68, kr1 = kr0 + 4 * 68;
            uint2 bh[4], bl[4];
            #pragma unroll
            for (int nf = 0; nf < 4; nf++) {
                int col = wn * 32 + nf * 8 + gid;
                uint2 kv0 = Kint[kr0 + col];
                uint2 kv1 = Kint[kr1 + col];
                bh[nf] = make_uint2(kv0.x, kv1.x);
                bl[nf] = make_uint2(kv0.y, kv1.y);
            }
            #pragma unroll
            for (int nf = 0; nf < 4; nf++) MMA_F16(s[nf], qh, bh[nf]);
            #pragma unroll
            for (int nf = 0; nf < 4; nf++) MMA_F16(s[nf], qh, bl[nf]);
            #pragma unroll
            for (int nf = 0; nf < 4; nf++) MMA_F16(s[nf], ql, bh[nf]);
        }

        const float* pb0 = pos_bias + ((size_t)h * SEQ + r0g) * SEQ + j0 + wn * 32 + tig * 2;
        const float* pb1 = pb0 + (size_t)8 * SEQ;
        #pragma unroll
        for (int nf = 0; nf < 4; nf++) {
            float2 b0 = *(const float2*)(pb0 + nf * 8);
            float2 b1 = *(const float2*)(pb1 + nf * 8);
            s[nf][0] += b0.x; s[nf][1] += b0.y;
            s[nf][2] += b1.x; s[nf][3] += b1.y;
        }
        if (jb == ib) {
            #pragma unroll
            for (int nf = 0; nf < 4; nf++) {
                int c = j0 + wn * 32 + nf * 8 + tig * 2;
                if (c > r0g)     s[nf][0] = -1e30f;
                if (c + 1 > r0g) s[nf][1] = -1e30f;
                if (c > r1g)     s[nf][2] = -1e30f;
                if (c + 1 > r1g) s[nf][3] = -1e30f;
            }
        }

        float rm0 = -1e30f, rm1 = -1e30f;
        #pragma unroll
        for (int nf = 0; nf < 4; nf++) {
            rm0 = fmaxf(rm0, fmaxf(s[nf][0], s[nf][1]));
            rm1 = fmaxf(rm1, fmaxf(s[nf][2], s[nf][3]));
        }
        rm0 = fmaxf(rm0, __shfl_xor_sync(0xffffffffu, rm0, 1));
        rm0 = fmaxf(rm0, __shfl_xor_sync(0xffffffffu, rm0, 2));
        rm1 = fmaxf(rm1, __shfl_xor_sync(0xffffffffu, rm1, 1));
        rm1 = fmaxf(rm1, __shfl_xor_sync(0xffffffffu, rm1, 2));
        srmax[wn * 64 + rl0] = rm0;
        srmax[wn * 64 + rl0 + 8] = rm1;
        __syncthreads();
        float bm0 = fmaxf(srmax[rl0], srmax[64 + rl0]);
        float bm1 = fmaxf(srmax[rl0 + 8], srmax[64 + rl0 + 8]);
        float mn0 = fmaxf(m0, bm0), mn1 = fmaxf(m1, bm1);
        float sc0 = __expf(m0 - mn0), sc1 = __expf(m1 - mn1);

        float rs0 = 0.f, rs1 = 0.f;
        #pragma unroll
        for (int nf = 0; nf < 4; nf++) {
            int pcol = wn * 16 + nf * 4 + tig;
            float p00 = __expf(s[nf][0] - mn0);
            float p01 = __expf(s[nf][1] - mn0);
            float p10 = __expf(s[nf][2] - mn1);
            float p11 = __expf(s[nf][3] - mn1);
            rs0 += p00 + p01; rs1 += p10 + p11;
            unsigned hw, lw;
            cvt_h2(p00, p01, hw, lw);
            Pint[rl0 * 36 + pcol] = make_uint2(hw, lw);
            cvt_h2(p10, p11, hw, lw);
            Pint[(rl0 + 8) * 36 + pcol] = make_uint2(hw, lw);
        }
        rs0 += __shfl_xor_sync(0xffffffffu, rs0, 1);
        rs0 += __shfl_xor_sync(0xffffffffu, rs0, 2);
        rs1 += __shfl_xor_sync(0xffffffffu, rs1, 1);
        rs1 += __shfl_xor_sync(0xffffffffu, rs1, 2);
        srsum[wn * 64 + rl0] = rs0;
        srsum[wn * 64 + rl0 + 8] = rs1;
        __syncthreads();
        l0 = l0 * sc0 + srsum[rl0] + srsum[64 + rl0];
        l1 = l1 * sc1 + srsum[rl0 + 8] + srsum[64 + rl0 + 8];
        m0 = mn0; m1 = mn1;

        #pragma unroll
        for (int nf = 0; nf < 8; nf++) {
            o[nf][0] *= sc0; o[nf][1] *= sc0;
            o[nf][2] *= sc1; o[nf][3] *= sc1;
        }
        #pragma unroll
        for (int c = 0; c < 4; c++) {
            uint2 p0 = Pint[rl0 * 36 + c * 8 + tig];
            uint2 p1 = Pint[(rl0 + 8) * 36 + c * 8 + tig];
            uint2 p2 = Pint[rl0 * 36 + c * 8 + 4 + tig];
            uint2 p3 = Pint[(rl0 + 8) * 36 + c * 8 + 4 + tig];
            uint4 ah = make_uint4(p0.x, p1.x, p2.x, p3.x);
            uint4 al = make_uint4(p0.y, p1.y, p2.y, p3.y);
            const int vr0 = (c * 8 + tig) * 132, vr1 = vr0 + 4 * 132;
            #pragma unroll
            for (int nf = 0; nf < 8; nf++) {
                int dcol = wn * 64 + nf * 8 + gid;
                uint2 vv0 = Vint[vr0 + dcol];
                uint2 vv1 = Vint[vr1 + dcol];
                uint2 bh = make_uint2(vv0.x, vv1.x);
                // PV 2-term: P_hi*V_hi + P_lo*V_hi (V_lo correction dropped,
                // error ~2^-12 relative; P rounding correction kept — it hits
                // the dominant softmax entry directly)
                MMA_F16(o[nf], ah, bh);
                MMA_F16(o[nf], al, bh);
            }
        }
    }

    // finalize + write interleaved ao planes
    float cnt0 = (float)(SEQ - 1 - r0g), cnt1 = (float)(SEQ - 1 - r1g);
    float mf0 = fmaxf(m0, MASKVF), mf1 = fmaxf(m1, MASKVF);
    float wu0 = __expf(m0 - mf0),  wu1 = __expf(m1 - mf1);
    float wk0 = __expf(MASKVF - mf0), wk1 = __expf(MASKVF - mf1);
    float iZ0 = 1.f / (l0 * wu0 + cnt0 * wk0);
    float iZ1 = 1.f / (l1 * wu1 + cnt1 * wk1);
    #pragma unroll
    for (int nf = 0; nf < 8; nf++) {
        int dcol = wn * 64 + nf * 8 + tig * 2;
        float2 vs0 = *(const float2*)&g_vsuf[(size_t)r0g * DHEAD + dcol];
        float2 vs1 = *(const float2*)&g_vsuf[(size_t)r1g * DHEAD + dcol];
        float o00 = (o[nf][0] * wu0 + wk0 * vs0.x) * iZ0;
        float o01 = (o[nf][1] * wu0 + wk0 * vs0.y) * iZ0;
        float o10 = (o[nf][2] * wu1 + wk1 * vs1.x) * iZ1;
        float o11 = (o[nf][3] * wu1 + wk1 * vs1.y) * iZ1;
        unsigned hw, lw;
        size_t u = (size_t)(h * DHEAD + dcol) >> 1;
        cvt_h2(o00, o01, hw, lw);
        g_ao2[(size_t)r0g * K2DIM + u] = make_uint2(hw, lw);
        cvt_h2(o10, o11, hw, lw);
        g_ao2[(size_t)r1g * K2DIM + u] = make_uint2(hw, lw);
    }
}

// ---------------- launch ---------------------------------------------------------
extern "C" void kernel_launch(void* const* d_in, const int* in_sizes, int n_in,
                              void* d_out, int out_size) {
    (void)in_sizes; (void)n_in; (void)out_size;
    const float* x        = (const float*)d_in[0];
    const float* pos_bias = (const float*)d_in[1];
    const float* gamma    = (const float*)d_in[2];
    const float* wq       = (const float*)d_in[3];
    const float* wk       = (const float*)d_in[4];
    const float* wv       = (const float*)d_in[5];
    const float* wo       = (const float*)d_in[6];
    float* out = (float*)d_out;

    uint2 *xn2_p, *wc2_p, *wo2_p, *ao2_p;
    cudaGetSymbolAddress((void**)&xn2_p, g_xn2);
    cudaGetSymbolAddress((void**)&wc2_p, g_wc2);
    cudaGetSymbolAddress((void**)&wo2_p, g_wo2);
    cudaGetSymbolAddress((void**)&ao2_p, g_ao2);

    const int GEMM_SMEM = 2 * 8192 * 4;      // 65536
    const int ATTN_SMEM = 22016 * 4;         // 88064
    cudaFuncSetAttribute((const void*)gemm_h2_kernel<0, 2>, cudaFuncAttributeMaxDynamicSharedMemorySize, GEMM_SMEM);
    cudaFuncSetAttribute((const void*)gemm_h2_kernel<1, 3>, cudaFuncAttributeMaxDynamicSharedMemorySize, GEMM_SMEM);
    cudaFuncSetAttribute((const void*)attn_mma_kernel, cudaFuncAttributeMaxDynamicSharedMemorySize, ATTN_SMEM);

    dim3 tb(32, 8);
    transpose_split_kernel<<<dim3(64, 64), tb>>>(wq, wc2_p, DIMM, SCALEF);
    transpose_split_kernel<<<dim3(4, 64), tb>>>(wk, wc2_p + (size_t)2048 * K2DIM, DHEAD, 1.0f);
    transpose_split_kernel<<<dim3(4, 64), tb>>>(wv, wc2_p + (size_t)2176 * K2DIM, DHEAD, 1.0f);
    transpose_split_kernel<<<dim3(64, 64), tb>>>(wo, wo2_p, DIMM, 1.0f);

    rmsnorm_split_kernel<<<SEQ, 256>>>(x, gamma);

    gemm_h2_kernel<1, 3><<<dim3(18, 16), 256, GEMM_SMEM>>>(xn2_p, wc2_p, nullptr, QKVN);

    vprep_kernel<<<512, 256>>>();
    vpart_kernel<<<16, 128>>>();
    vsuf_kernel<<<16, 128>>>();

    attn_mma_kernel<<<dim3(32, HEADS), 256, ATTN_SMEM>>>(pos_bias);

    gemm_h2_kernel<0, 2><<<dim3(16, 16), 256, GEMM_SMEM>>>(ao2_p, wo2_p, out, DIMM);
}

// round 10
// speedup vs baseline: 1.2275x; 1.0951x over previous
#include <cuda_runtime.h>
#include <cuda_fp16.h>
#include <math.h>
#include <stddef.h>
#include <stdint.h>

#define SEQ    2048
#define DIMM   2048
#define HEADS  16
#define DHEAD  128
#define QKVN   2304
#define K2DIM  1024          // K/2 half2 units per row
#define EPSF   1e-5f
#define MASKVF 1e-10f
#define SCALEF 0.08838834764831845f

// ---------------- scratch (hi/lo interleaved as uint2 {h,l}) -----------------
__device__ uint2    g_xn2[SEQ * K2DIM];
__device__ uint2    g_wc2[QKVN * K2DIM];     // [wq|wk|wv]^T (q pre-scaled)
__device__ uint2    g_wo2[DIMM * K2DIM];
__device__ uint2    g_ao2[SEQ * K2DIM];
__device__ uint4    g_qh4[HEADS * 128 * 8 * 32];   // Q fragments hi
__device__ uint4    g_ql4[HEADS * 128 * 8 * 32];   // Q fragments lo
__device__ uint2    g_kt2[64 * SEQ];         // K^T half2-packed along d, {h,l}
__device__ float    g_v[SEQ * DHEAD];        // V dense fp32
__device__ uint2    g_vt2[(SEQ / 2) * DHEAD];
__device__ float    g_vsuf[SEQ * DHEAD];
__device__ float    g_vpart[16 * DHEAD];

// ---------------- helpers ----------------------------------------------------
__device__ __forceinline__ void cvt_h2(float x0, float x1, unsigned& h, unsigned& l) {
    __half2 hh = __floats2half2_rn(x0, x1);
    __half2 ll = __floats2half2_rn(x0 - __low2float(hh), x1 - __high2float(hh));
    h = *reinterpret_cast<unsigned*>(&hh);
    l = *reinterpret_cast<unsigned*>(&ll);
}
#define MMA_F16(Cacc, Av, Bv)                                               \
    asm volatile("mma.sync.aligned.m16n8k16.row.col.f32.f16.f16.f32 "       \
        "{%0,%1,%2,%3}, {%4,%5,%6,%7}, {%8,%9}, {%0,%1,%2,%3};"             \
        : "+f"((Cacc)[0]), "+f"((Cacc)[1]), "+f"((Cacc)[2]), "+f"((Cacc)[3])\
        : "r"((Av).x), "r"((Av).y), "r"((Av).z), "r"((Av).w),               \
          "r"((Bv).x), "r"((Bv).y))

// ---------------- RMSNorm -> interleaved half2 hi/lo --------------------------
__global__ void rmsnorm_split_kernel(const float* __restrict__ x,
                                     const float* __restrict__ gamma) {
    int row = blockIdx.x;
    const float* xr = x + (size_t)row * DIMM;
    float ss = 0.f;
    for (int i = threadIdx.x; i < DIMM; i += 256) { float v = xr[i]; ss += v * v; }
    __shared__ float red[8];
    #pragma unroll
    for (int o = 16; o; o >>= 1) ss += __shfl_xor_sync(0xffffffffu, ss, o);
    if ((threadIdx.x & 31) == 0) red[threadIdx.x >> 5] = ss;
    __syncthreads();
    if (threadIdx.x < 32) {
        float v = (threadIdx.x < 8) ? red[threadIdx.x] : 0.f;
        #pragma unroll
        for (int o = 4; o; o >>= 1) v += __shfl_xor_sync(0xffffffffu, v, o);
        if (threadIdx.x == 0) red[0] = v;
    }
    __syncthreads();
    float inv = rsqrtf(red[0] / (float)DIMM + EPSF);
    for (int u = threadIdx.x; u < K2DIM; u += 256) {
        float2 xv = *(const float2*)(xr + 2 * u);
        float2 gv = *(const float2*)(gamma + 2 * u);
        unsigned h, l;
        cvt_h2(xv.x * inv * gv.x, xv.y * inv * gv.y, h, l);
        g_xn2[(size_t)row * K2DIM + u] = make_uint2(h, l);
    }
}

// ---------------- transpose + split -> interleaved ----------------------------
__global__ void transpose_split_kernel(const float* __restrict__ src,
                                       uint2* __restrict__ dst,
                                       int C, float scale) {
    __shared__ float tile[32][33];
    int bx = blockIdx.x * 32, by = blockIdx.y * 32;   // bx: n, by: k
    int tx = threadIdx.x, ty = threadIdx.y;           // 32 x 8
    #pragma unroll
    for (int j = 0; j < 32; j += 8)
        tile[ty + j][tx] = src[(size_t)(by + ty + j) * C + bx + tx];
    __syncthreads();
    int ul = tx & 15, nb = ty * 2 + (tx >> 4);
    #pragma unroll
    for (int rep = 0; rep < 2; rep++) {
        int nl = nb + rep * 16;
        float v0 = tile[2 * ul][nl] * scale;
        float v1 = tile[2 * ul + 1][nl] * scale;
        unsigned h, l;
        cvt_h2(v0, v1, h, l);
        dst[(size_t)(bx + nl) * K2DIM + (by >> 1) + ul] = make_uint2(h, l);
    }
}

// ---------------- fp16 split GEMM (proven in R9) ------------------------------
template <int EPI, int TERMS>
__global__ __launch_bounds__(256) void gemm_h2_kernel(
    const uint2* __restrict__ A2, const uint2* __restrict__ B2,
    float* __restrict__ C, int N)
{
    extern __shared__ unsigned smu[];
    const int tid = threadIdx.x, lane = tid & 31, warp = tid >> 5;
    const int m0 = blockIdx.y << 7, n0 = blockIdx.x << 7;
    const int wm = warp >> 1, wn = warp & 1;
    const int gid = lane >> 2, tig = lane & 3;

    float acc[2][8][4];
    #pragma unroll
    for (int mf = 0; mf < 2; mf++)
        #pragma unroll
        for (int nf = 0; nf < 8; nf++)
            #pragma unroll
            for (int q = 0; q < 4; q++) acc[mf][nf][q] = 0.f;

    uint2 ra2[2][4], rb2[4][2];
    const int arow = m0 + warp * 16 + gid;

    #pragma unroll
    for (int i = 0; i < 2; i++) {
        int u0 = 8 * i + tig;
        ra2[i][0] = A2[(size_t)arow * K2DIM + u0];
        ra2[i][1] = A2[(size_t)(arow + 8) * K2DIM + u0];
        ra2[i][2] = A2[(size_t)arow * K2DIM + u0 + 4];
        ra2[i][3] = A2[(size_t)(arow + 8) * K2DIM + u0 + 4];
    }
    #pragma unroll
    for (int j = 0; j < 4; j++) {
        int n = n0 + (warp + 8 * (j & 1)) * 8 + gid;
        int u0 = (j >> 1) * 8 + tig;
        rb2[j][0] = B2[(size_t)n * K2DIM + u0];
        rb2[j][1] = B2[(size_t)n * K2DIM + u0 + 4];
    }

    const int S = 64;
    for (int s = 0; s < S; s++) {
        unsigned* buf = smu + (s & 1) * 8192;
        uint4* Ah4 = (uint4*)buf;
        uint4* Al4 = (uint4*)(buf + 2048);
        uint2* Bh2 = (uint2*)(buf + 4096);
        uint2* Bl2 = (uint2*)(buf + 6144);

        #pragma unroll
        for (int i = 0; i < 2; i++) {
            int slot = warp + 8 * i;
            Ah4[slot * 32 + lane] = make_uint4(ra2[i][0].x, ra2[i][1].x, ra2[i][2].x, ra2[i][3].x);
            Al4[slot * 32 + lane] = make_uint4(ra2[i][0].y, ra2[i][1].y, ra2[i][2].y, ra2[i][3].y);
        }
        #pragma unroll
        for (int j = 0; j < 4; j++) {
            int slot = (j >> 1) * 16 + warp + 8 * (j & 1);
            Bh2[slot * 32 + lane] = make_uint2(rb2[j][0].x, rb2[j][1].x);
            Bl2[slot * 32 + lane] = make_uint2(rb2[j][0].y, rb2[j][1].y);
        }
        __syncthreads();

        if (s + 1 < S) {
            const int ub = (s + 1) << 4;
            #pragma unroll
            for (int i = 0; i < 2; i++) {
                int u0 = ub + 8 * i + tig;
                ra2[i][0] = A2[(size_t)arow * K2DIM + u0];
                ra2[i][1] = A2[(size_t)(arow + 8) * K2DIM + u0];
                ra2[i][2] = A2[(size_t)arow * K2DIM + u0 + 4];
                ra2[i][3] = A2[(size_t)(arow + 8) * K2DIM + u0 + 4];
            }
            #pragma unroll
            for (int j = 0; j < 4; j++) {
                int n = n0 + (warp + 8 * (j & 1)) * 8 + gid;
                int u0 = ub + (j >> 1) * 8 + tig;
                rb2[j][0] = B2[(size_t)n * K2DIM + u0];
                rb2[j][1] = B2[(size_t)n * K2DIM + u0 + 4];
            }
        }

        #pragma unroll
        for (int kk = 0; kk < 2; kk++) {
            uint4 ah[2], al[2];
            uint2 bh[8], bl[8];
            #pragma unroll
            for (int mf = 0; mf < 2; mf++) {
                int slot = kk * 8 + wm * 2 + mf;
                ah[mf] = Ah4[slot * 32 + lane];
                al[mf] = Al4[slot * 32 + lane];
            }
            #pragma unroll
            for (int nf = 0; nf < 8; nf++) {
                int slot = kk * 16 + wn * 8 + nf;
                bh[nf] = Bh2[slot * 32 + lane];
                bl[nf] = Bl2[slot * 32 + lane];
            }
            #pragma unroll
            for (int nf = 0; nf < 8; nf++)
                #pragma unroll
                for (int mf = 0; mf < 2; mf++)
                    MMA_F16(acc[mf][nf], ah[mf], bh[nf]);
            #pragma unroll
            for (int nf = 0; nf < 8; nf++)
                #pragma unroll
                for (int mf = 0; mf < 2; mf++)
                    MMA_F16(acc[mf][nf], ah[mf], bl[nf]);
            if (TERMS == 3) {
                #pragma unroll
                for (int nf = 0; nf < 8; nf++)
                    #pragma unroll
                    for (int mf = 0; mf < 2; mf++)
                        MMA_F16(acc[mf][nf], al[mf], bh[nf]);
            }
        }
        __syncthreads();
    }

    if (EPI == 0) {
        #pragma unroll
        for (int mf = 0; mf < 2; mf++) {
            const int r0 = m0 + wm * 32 + mf * 16 + gid;
            #pragma unroll
            for (int nf = 0; nf < 8; nf++) {
                const int c = n0 + wn * 64 + nf * 8 + tig * 2;
                *(float2*)(C + (size_t)r0 * N + c) = make_float2(acc[mf][nf][0], acc[mf][nf][1]);
                *(float2*)(C + (size_t)(r0 + 8) * N + c) = make_float2(acc[mf][nf][2], acc[mf][nf][3]);
            }
        }
    } else {
        const int bx = blockIdx.x;
        if (bx < 16) {
            const int h = bx;
            #pragma unroll
            for (int mf = 0; mf < 2; mf++) {
                int rg = (m0 >> 4) + wm * 2 + mf;
                #pragma unroll
                for (int k2 = 0; k2 < 4; k2++) {
                    int kkg = wn * 4 + k2;
                    const float* e = acc[mf][2 * k2];
                    const float* o = acc[mf][2 * k2 + 1];
                    uint4 hv, lv;
                    cvt_h2(e[0], e[1], hv.x, lv.x);
                    cvt_h2(e[2], e[3], hv.y, lv.y);
                    cvt_h2(o[0], o[1], hv.z, lv.z);
                    cvt_h2(o[2], o[3], hv.w, lv.w);
                    size_t idx = ((size_t)(h * 128 + rg) * 8 + kkg) * 32 + lane;
                    g_qh4[idx] = hv;
                    g_ql4[idx] = lv;
                }
            }
        } else if (bx == 16) {
            #pragma unroll
            for (int mf = 0; mf < 2; mf++) {
                int j = m0 + wm * 32 + mf * 16 + gid;
                #pragma unroll
                for (int nf = 0; nf < 8; nf++) {
                    int d2 = wn * 32 + nf * 4 + tig;
                    unsigned h0, l0, h1, l1;
                    cvt_h2(acc[mf][nf][0], acc[mf][nf][1], h0, l0);
                    cvt_h2(acc[mf][nf][2], acc[mf][nf][3], h1, l1);
                    g_kt2[d2 * SEQ + j]     = make_uint2(h0, l0);
                    g_kt2[d2 * SEQ + j + 8] = make_uint2(h1, l1);
                }
            }
        } else {
            #pragma unroll
            for (int mf = 0; mf < 2; mf++) {
                int j = m0 + wm * 32 + mf * 16 + gid;
                #pragma unroll
                for (int nf = 0; nf < 8; nf++) {
                    int d = wn * 64 + nf * 8 + tig * 2;
                    *(float2*)&g_v[(size_t)j * DHEAD + d] =
                        make_float2(acc[mf][nf][0], acc[mf][nf][1]);
                    *(float2*)&g_v[(size_t)(j + 8) * DHEAD + d] =
                        make_float2(acc[mf][nf][2], acc[mf][nf][3]);
                }
            }
        }
    }
}

// ---------------- V j-paired interleaved half2 planes --------------------------
__global__ void vprep_kernel() {
    int t = blockIdx.x * 256 + threadIdx.x;     // 131072
    int d = t & 127, j2 = t >> 7;
    float v0 = g_v[(size_t)(2 * j2) * DHEAD + d];
    float v1 = g_v[(size_t)(2 * j2 + 1) * DHEAD + d];
    unsigned h, l;
    cvt_h2(v0, v1, h, l);
    g_vt2[j2 * DHEAD + d] = make_uint2(h, l);
}

// ---------------- V suffix sums ------------------------------------------------
__global__ void vpart_kernel() {
    int blk = blockIdx.x, d = threadIdx.x;
    float s = 0.f;
    #pragma unroll 8
    for (int r = 0; r < 128; r++)
        s += g_v[(size_t)(blk * 128 + r) * DHEAD + d];
    g_vpart[blk * DHEAD + d] = s;
}
__global__ void vsuf_kernel() {
    int blk = blockIdx.x, d = threadIdx.x;
    float acc = 0.f;
    for (int b = blk + 1; b < 16; b++) acc += g_vpart[b * DHEAD + d];
    #pragma unroll 4
    for (int r = 127; r >= 0; r--) {
        int row = blk * 128 + r;
        g_vsuf[(size_t)row * DHEAD + d] = acc;
        acc += g_v[(size_t)row * DHEAD + d];
    }
}

// ---------------- row-owning fp16 tensor-core flash attention -------------------
// i-tile 128 rows, 8 warps x 16 rows, each warp covers all 64 j-cols.
// Softmax fully warp-local (quad shuffles); P stays in registers
// (QK C-fragment == PV A-fragment layout).  QK x3, PV 2-term.
// smem uint2: Kint[64][68]@0 (4352), Vint[32][132]@4352 (4224) = 8576 uint2.
__global__ __launch_bounds__(256, 1) void attn_mma_kernel(const float* __restrict__ pos_bias) {
    extern __shared__ float sm[];
    uint2* Kint = (uint2*)sm;
    uint2* Vint = (uint2*)sm + 4352;

    const int h  = blockIdx.y;
    const int ib = gridDim.x - 1 - blockIdx.x;       // big i-tiles first
    const int i0 = ib * 128;
    const int tid = threadIdx.x, lane = tid & 31, warp = tid >> 5;
    const int gid = lane >> 2, tig = lane & 3;

    const int rg = (i0 >> 4) + warp;                  // 16-row group id
    const size_t qbase = ((size_t)(h * 128 + rg) * 8) * 32 + lane;

    const int jl = tid & 63, cb = tid >> 6;
    const int r0g = i0 + warp * 16 + gid, r1g = r0g + 8;
    const int jd = 2 * ib + (warp >> 2);              // this warp's diagonal block
    const int jbmax = 2 * ib + 1;

    float o[16][4];
    #pragma unroll
    for (int nf = 0; nf < 16; nf++)
        #pragma unroll
        for (int q = 0; q < 4; q++) o[nf][q] = 0.f;
    float m0 = -1e30f, m1 = -1e30f, l0 = 0.f, l1 = 0.f;

    for (int jb = 0; jb <= jbmax; jb++) {
        const int j0 = jb * 64;
        __syncthreads();
        #pragma unroll
        for (int it = 0; it < 16; it++) {
            int d2 = cb * 16 + it;
            Kint[d2 * 68 + jl] = g_kt2[d2 * SEQ + j0 + jl];
        }
        #pragma unroll
        for (int it = 0; it < 16; it++) {
            int idx = it * 256 + tid;
            int j2 = idx >> 7, d = idx & 127;
            Vint[j2 * 132 + d] = g_vt2[(j0 / 2 + j2) * DHEAD + d];
        }
        __syncthreads();

        if (jb > jd) continue;    // past this warp's causal frontier

        // ---- S = Q K^T (fp16 x3), 8 nf over all 64 columns
        float s[8][4];
        #pragma unroll
        for (int nf = 0; nf < 8; nf++)
            #pragma unroll
            for (int q = 0; q < 4; q++) s[nf][q] = 0.f;

        #pragma unroll
        for (int kk = 0; kk < 8; kk++) {
            uint4 qh = g_qh4[qbase + kk * 32];
            uint4 ql = g_ql4[qbase + kk * 32];
            const int kr0 = (kk * 8 + tig) * 68, kr1 = kr0 + 4 * 68;
            uint2 bh[8], bl[8];
            #pragma unroll
            for (int nf = 0; nf < 8; nf++) {
                int col = nf * 8 + gid;
                uint2 kv0 = Kint[kr0 + col];
                uint2 kv1 = Kint[kr1 + col];
                bh[nf] = make_uint2(kv0.x, kv1.x);
                bl[nf] = make_uint2(kv0.y, kv1.y);
            }
            #pragma unroll
            for (int nf = 0; nf < 8; nf++) MMA_F16(s[nf], qh, bh[nf]);
            #pragma unroll
            for (int nf = 0; nf < 8; nf++) MMA_F16(s[nf], qh, bl[nf]);
            #pragma unroll
            for (int nf = 0; nf < 8; nf++) MMA_F16(s[nf], ql, bh[nf]);
        }

        // ---- + pos_bias, causal mask on this warp's diagonal block
        const float* pb0 = pos_bias + ((size_t)h * SEQ + r0g) * SEQ + j0 + tig * 2;
        const float* pb1 = pb0 + (size_t)8 * SEQ;
        #pragma unroll
        for (int nf = 0; nf < 8; nf++) {
            float2 b0 = *(const float2*)(pb0 + nf * 8);
            float2 b1 = *(const float2*)(pb1 + nf * 8);
            s[nf][0] += b0.x; s[nf][1] += b0.y;
            s[nf][2] += b1.x; s[nf][3] += b1.y;
        }
        if (jb == jd) {
            #pragma unroll
            for (int nf = 0; nf < 8; nf++) {
                int c = j0 + nf * 8 + tig * 2;
                if (c > r0g)     s[nf][0] = -1e30f;
                if (c + 1 > r0g) s[nf][1] = -1e30f;
                if (c > r1g)     s[nf][2] = -1e30f;
                if (c + 1 > r1g) s[nf][3] = -1e30f;
            }
        }

        // ---- warp-local row max (quad shuffles only)
        float rm0 = -1e30f, rm1 = -1e30f;
        #pragma unroll
        for (int nf = 0; nf < 8; nf++) {
            rm0 = fmaxf(rm0, fmaxf(s[nf][0], s[nf][1]));
            rm1 = fmaxf(rm1, fmaxf(s[nf][2], s[nf][3]));
        }
        rm0 = fmaxf(rm0, __shfl_xor_sync(0xffffffffu, rm0, 1));
        rm0 = fmaxf(rm0, __shfl_xor_sync(0xffffffffu, rm0, 2));
        rm1 = fmaxf(rm1, __shfl_xor_sync(0xffffffffu, rm1, 1));
        rm1 = fmaxf(rm1, __shfl_xor_sync(0xffffffffu, rm1, 2));
        float mn0 = fmaxf(m0, rm0), mn1 = fmaxf(m1, rm1);
        float sc0 = __expf(m0 - mn0), sc1 = __expf(m1 - mn1);

        // ---- exp + in-register P fragments (A-frag layout) + row sums
        float rs0 = 0.f, rs1 = 0.f;
        uint4 pah[4], pal[4];
        #pragma unroll
        for (int c = 0; c < 4; c++) {
            float p00 = __expf(s[2*c][0] - mn0);
            float p01 = __expf(s[2*c][1] - mn0);
            float p02 = __expf(s[2*c][2] - mn1);
            float p03 = __expf(s[2*c][3] - mn1);
            float p10 = __expf(s[2*c+1][0] - mn0);
            float p11 = __expf(s[2*c+1][1] - mn0);
            float p12 = __expf(s[2*c+1][2] - mn1);
            float p13 = __expf(s[2*c+1][3] - mn1);
            rs0 += p00 + p01 + p10 + p11;
            rs1 += p02 + p03 + p12 + p13;
            cvt_h2(p00, p01, pah[c].x, pal[c].x);   // row gid,   k=tig*2..+1
            cvt_h2(p02, p03, pah[c].y, pal[c].y);   // row gid+8
            cvt_h2(p10, p11, pah[c].z, pal[c].z);   // row gid,   k+8
            cvt_h2(p12, p13, pah[c].w, pal[c].w);   // row gid+8, k+8
        }
        rs0 += __shfl_xor_sync(0xffffffffu, rs0, 1);
        rs0 += __shfl_xor_sync(0xffffffffu, rs0, 2);
        rs1 += __shfl_xor_sync(0xffffffffu, rs1, 1);
        rs1 += __shfl_xor_sync(0xffffffffu, rs1, 2);
        l0 = l0 * sc0 + rs0;
        l1 = l1 * sc1 + rs1;
        m0 = mn0; m1 = mn1;

        // ---- rescale O, then O += P V (PV 2-term: P_hi*V_hi + P_lo*V_hi)
        #pragma unroll
        for (int nf = 0; nf < 16; nf++) {
            o[nf][0] *= sc0; o[nf][1] *= sc0;
            o[nf][2] *= sc1; o[nf][3] *= sc1;
        }
        #pragma unroll
        for (int c = 0; c < 4; c++) {
            const int vr0 = (c * 8 + tig) * 132, vr1 = vr0 + 4 * 132;
            #pragma unroll
            for (int nf = 0; nf < 16; nf++) {
                int dcol = nf * 8 + gid;
                uint2 vv0 = Vint[vr0 + dcol];
                uint2 vv1 = Vint[vr1 + dcol];
                uint2 bh = make_uint2(vv0.x, vv1.x);
                MMA_F16(o[nf], pah[c], bh);
                MMA_F16(o[nf], pal[c], bh);
            }
        }
    }

    // ---- finalize with analytic MASK_VALUE tail; write interleaved ao planes
    float cnt0 = (float)(SEQ - 1 - r0g), cnt1 = (float)(SEQ - 1 - r1g);
    float mf0 = fmaxf(m0, MASKVF), mf1 = fmaxf(m1, MASKVF);
    float wu0 = __expf(m0 - mf0),  wu1 = __expf(m1 - mf1);
    float wk0 = __expf(MASKVF - mf0), wk1 = __expf(MASKVF - mf1);
    float iZ0 = 1.f / (l0 * wu0 + cnt0 * wk0);
    float iZ1 = 1.f / (l1 * wu1 + cnt1 * wk1);
    #pragma unroll
    for (int nf = 0; nf < 16; nf++) {
        int dcol = nf * 8 + tig * 2;
        float2 vs0 = *(const float2*)&g_vsuf[(size_t)r0g * DHEAD + dcol];
        float2 vs1 = *(const float2*)&g_vsuf[(size_t)r1g * DHEAD + dcol];
        float o00 = (o[nf][0] * wu0 + wk0 * vs0.x) * iZ0;
        float o01 = (o[nf][1] * wu0 + wk0 * vs0.y) * iZ0;
        float o10 = (o[nf][2] * wu1 + wk1 * vs1.x) * iZ1;
        float o11 = (o[nf][3] * wu1 + wk1 * vs1.y) * iZ1;
        unsigned hw, lw;
        size_t u = (size_t)(h * DHEAD + dcol) >> 1;
        cvt_h2(o00, o01, hw, lw);
        g_ao2[(size_t)r0g * K2DIM + u] = make_uint2(hw, lw);
        cvt_h2(o10, o11, hw, lw);
        g_ao2[(size_t)r1g * K2DIM + u] = make_uint2(hw, lw);
    }
}

// ---------------- launch ---------------------------------------------------------
extern "C" void kernel_launch(void* const* d_in, const int* in_sizes, int n_in,
                              void* d_out, int out_size) {
    (void)in_sizes; (void)n_in; (void)out_size;
    const float* x        = (const float*)d_in[0];
    const float* pos_bias = (const float*)d_in[1];
    const float* gamma    = (const float*)d_in[2];
    const float* wq       = (const float*)d_in[3];
    const float* wk       = (const float*)d_in[4];
    const float* wv       = (const float*)d_in[5];
    const float* wo       = (const float*)d_in[6];
    float* out = (float*)d_out;

    uint2 *xn2_p, *wc2_p, *wo2_p, *ao2_p;
    cudaGetSymbolAddress((void**)&xn2_p, g_xn2);
    cudaGetSymbolAddress((void**)&wc2_p, g_wc2);
    cudaGetSymbolAddress((void**)&wo2_p, g_wo2);
    cudaGetSymbolAddress((void**)&ao2_p, g_ao2);

    const int GEMM_SMEM = 2 * 8192 * 4;      // 65536
    const int ATTN_SMEM = 8576 * 8;          // 68608 (Kint + Vint, uint2)
    cudaFuncSetAttribute((const void*)gemm_h2_kernel<0, 2>, cudaFuncAttributeMaxDynamicSharedMemorySize, GEMM_SMEM);
    cudaFuncSetAttribute((const void*)gemm_h2_kernel<1, 3>, cudaFuncAttributeMaxDynamicSharedMemorySize, GEMM_SMEM);
    cudaFuncSetAttribute((const void*)attn_mma_kernel, cudaFuncAttributeMaxDynamicSharedMemorySize, ATTN_SMEM);

    dim3 tb(32, 8);
    transpose_split_kernel<<<dim3(64, 64), tb>>>(wq, wc2_p, DIMM, SCALEF);
    transpose_split_kernel<<<dim3(4, 64), tb>>>(wk, wc2_p + (size_t)2048 * K2DIM, DHEAD, 1.0f);
    transpose_split_kernel<<<dim3(4, 64), tb>>>(wv, wc2_p + (size_t)2176 * K2DIM, DHEAD, 1.0f);
    transpose_split_kernel<<<dim3(64, 64), tb>>>(wo, wo2_p, DIMM, 1.0f);

    rmsnorm_split_kernel<<<SEQ, 256>>>(x, gamma);

    gemm_h2_kernel<1, 3><<<dim3(18, 16), 256, GEMM_SMEM>>>(xn2_p, wc2_p, nullptr, QKVN);

    vprep_kernel<<<512, 256>>>();
    vpart_kernel<<<16, 128>>>();
    vsuf_kernel<<<16, 128>>>();

    attn_mma_kernel<<<dim3(16, HEADS), 256, ATTN_SMEM>>>(pos_bias);

    gemm_h2_kernel<0, 2><<<dim3(16, 16), 256, GEMM_SMEM>>>(ao2_p, wo2_p, out, DIMM);
}

// round 11
// speedup vs baseline: 1.3911x; 1.1333x over previous
#include <cuda_runtime.h>
#include <cuda_fp16.h>
#include <math.h>
#include <stddef.h>
#include <stdint.h>

#define SEQ    2048
#define DIMM   2048
#define HEADS  16
#define DHEAD  128
#define QKVN   2304
#define K2DIM  1024          // K/2 half2 units per row
#define EPSF   1e-5f
#define MASKVF 1e-10f
#define SCALEF 0.08838834764831845f

// ---------------- scratch (hi/lo interleaved as uint2 {h,l}) -----------------
__device__ uint2    g_xn2[SEQ * K2DIM];
__device__ uint2    g_wc2[QKVN * K2DIM];     // [wq|wk|wv]^T (q pre-scaled)
__device__ uint2    g_wo2[DIMM * K2DIM];
__device__ uint2    g_ao2[SEQ * K2DIM];
__device__ uint4    g_qh4[HEADS * 128 * 8 * 32];   // Q fragments hi
__device__ uint4    g_ql4[HEADS * 128 * 8 * 32];   // Q fragments lo
__device__ uint2    g_kt2[64 * SEQ];         // K^T half2-packed along d, {h,l}
__device__ float    g_v[SEQ * DHEAD];        // V dense fp32
__device__ uint2    g_vt2[(SEQ / 2) * DHEAD];
__device__ float    g_vsuf[SEQ * DHEAD];
__device__ float    g_vpart[16 * DHEAD];

// ---------------- helpers ----------------------------------------------------
__device__ __forceinline__ void cvt_h2(float x0, float x1, unsigned& h, unsigned& l) {
    __half2 hh = __floats2half2_rn(x0, x1);
    __half2 ll = __floats2half2_rn(x0 - __low2float(hh), x1 - __high2float(hh));
    h = *reinterpret_cast<unsigned*>(&hh);
    l = *reinterpret_cast<unsigned*>(&ll);
}
__device__ __forceinline__ unsigned cvt_h(float x0, float x1) {
    __half2 hh = __floats2half2_rn(x0, x1);
    return *reinterpret_cast<unsigned*>(&hh);
}
#define MMA_F16(Cacc, Av, Bv)                                               \
    asm volatile("mma.sync.aligned.m16n8k16.row.col.f32.f16.f16.f32 "       \
        "{%0,%1,%2,%3}, {%4,%5,%6,%7}, {%8,%9}, {%0,%1,%2,%3};"             \
        : "+f"((Cacc)[0]), "+f"((Cacc)[1]), "+f"((Cacc)[2]), "+f"((Cacc)[3])\
        : "r"((Av).x), "r"((Av).y), "r"((Av).z), "r"((Av).w),               \
          "r"((Bv).x), "r"((Bv).y))

// ---------------- RMSNorm -> interleaved half2 hi/lo --------------------------
__global__ void rmsnorm_split_kernel(const float* __restrict__ x,
                                     const float* __restrict__ gamma) {
    int row = blockIdx.x;
    const float* xr = x + (size_t)row * DIMM;
    float ss = 0.f;
    for (int i = threadIdx.x; i < DIMM; i += 256) { float v = xr[i]; ss += v * v; }
    __shared__ float red[8];
    #pragma unroll
    for (int o = 16; o; o >>= 1) ss += __shfl_xor_sync(0xffffffffu, ss, o);
    if ((threadIdx.x & 31) == 0) red[threadIdx.x >> 5] = ss;
    __syncthreads();
    if (threadIdx.x < 32) {
        float v = (threadIdx.x < 8) ? red[threadIdx.x] : 0.f;
        #pragma unroll
        for (int o = 4; o; o >>= 1) v += __shfl_xor_sync(0xffffffffu, v, o);
        if (threadIdx.x == 0) red[0] = v;
    }
    __syncthreads();
    float inv = rsqrtf(red[0] / (float)DIMM + EPSF);
    for (int u = threadIdx.x; u < K2DIM; u += 256) {
        float2 xv = *(const float2*)(xr + 2 * u);
        float2 gv = *(const float2*)(gamma + 2 * u);
        unsigned h, l;
        cvt_h2(xv.x * inv * gv.x, xv.y * inv * gv.y, h, l);
        g_xn2[(size_t)row * K2DIM + u] = make_uint2(h, l);
    }
}

// ---------------- transpose + split -> interleaved ----------------------------
__global__ void transpose_split_kernel(const float* __restrict__ src,
                                       uint2* __restrict__ dst,
                                       int C, float scale) {
    __shared__ float tile[32][33];
    int bx = blockIdx.x * 32, by = blockIdx.y * 32;   // bx: n, by: k
    int tx = threadIdx.x, ty = threadIdx.y;           // 32 x 8
    #pragma unroll
    for (int j = 0; j < 32; j += 8)
        tile[ty + j][tx] = src[(size_t)(by + ty + j) * C + bx + tx];
    __syncthreads();
    int ul = tx & 15, nb = ty * 2 + (tx >> 4);
    #pragma unroll
    for (int rep = 0; rep < 2; rep++) {
        int nl = nb + rep * 16;
        float v0 = tile[2 * ul][nl] * scale;
        float v1 = tile[2 * ul + 1][nl] * scale;
        unsigned h, l;
        cvt_h2(v0, v1, h, l);
        dst[(size_t)(bx + nl) * K2DIM + (by >> 1) + ul] = make_uint2(h, l);
    }
}

// ---------------- fp16 split GEMM ---------------------------------------------
// TERMS: 3 = ah*bh + ah*bl + al*bh; 2 = ah*bh + ah*bl; 1 = ah*bh (pure fp16).
// Lo-plane staging compiled out when unused.
template <int EPI, int TERMS>
__global__ __launch_bounds__(256) void gemm_h2_kernel(
    const uint2* __restrict__ A2, const uint2* __restrict__ B2,
    float* __restrict__ C, int N)
{
    extern __shared__ unsigned smu[];
    const int tid = threadIdx.x, lane = tid & 31, warp = tid >> 5;
    const int m0 = blockIdx.y << 7, n0 = blockIdx.x << 7;
    const int wm = warp >> 1, wn = warp & 1;
    const int gid = lane >> 2, tig = lane & 3;

    float acc[2][8][4];
    #pragma unroll
    for (int mf = 0; mf < 2; mf++)
        #pragma unroll
        for (int nf = 0; nf < 8; nf++)
            #pragma unroll
            for (int q = 0; q < 4; q++) acc[mf][nf][q] = 0.f;

    uint2 ra2[2][4], rb2[4][2];
    const int arow = m0 + warp * 16 + gid;

    #pragma unroll
    for (int i = 0; i < 2; i++) {
        int u0 = 8 * i + tig;
        ra2[i][0] = A2[(size_t)arow * K2DIM + u0];
        ra2[i][1] = A2[(size_t)(arow + 8) * K2DIM + u0];
        ra2[i][2] = A2[(size_t)arow * K2DIM + u0 + 4];
        ra2[i][3] = A2[(size_t)(arow + 8) * K2DIM + u0 + 4];
    }
    #pragma unroll
    for (int j = 0; j < 4; j++) {
        int n = n0 + (warp + 8 * (j & 1)) * 8 + gid;
        int u0 = (j >> 1) * 8 + tig;
        rb2[j][0] = B2[(size_t)n * K2DIM + u0];
        rb2[j][1] = B2[(size_t)n * K2DIM + u0 + 4];
    }

    const int S = 64;
    for (int s = 0; s < S; s++) {
        unsigned* buf = smu + (s & 1) * 8192;
        uint4* Ah4 = (uint4*)buf;
        uint4* Al4 = (uint4*)(buf + 2048);
        uint2* Bh2 = (uint2*)(buf + 4096);
        uint2* Bl2 = (uint2*)(buf + 6144);

        #pragma unroll
        for (int i = 0; i < 2; i++) {
            int slot = warp + 8 * i;
            Ah4[slot * 32 + lane] = make_uint4(ra2[i][0].x, ra2[i][1].x, ra2[i][2].x, ra2[i][3].x);
            if (TERMS == 3)
                Al4[slot * 32 + lane] = make_uint4(ra2[i][0].y, ra2[i][1].y, ra2[i][2].y, ra2[i][3].y);
        }
        #pragma unroll
        for (int j = 0; j < 4; j++) {
            int slot = (j >> 1) * 16 + warp + 8 * (j & 1);
            Bh2[slot * 32 + lane] = make_uint2(rb2[j][0].x, rb2[j][1].x);
            if (TERMS >= 2)
                Bl2[slot * 32 + lane] = make_uint2(rb2[j][0].y, rb2[j][1].y);
        }
        __syncthreads();

        if (s + 1 < S) {
            const int ub = (s + 1) << 4;
            #pragma unroll
            for (int i = 0; i < 2; i++) {
                int u0 = ub + 8 * i + tig;
                ra2[i][0] = A2[(size_t)arow * K2DIM + u0];
                ra2[i][1] = A2[(size_t)(arow + 8) * K2DIM + u0];
                ra2[i][2] = A2[(size_t)arow * K2DIM + u0 + 4];
                ra2[i][3] = A2[(size_t)(arow + 8) * K2DIM + u0 + 4];
            }
            #pragma unroll
            for (int j = 0; j < 4; j++) {
                int n = n0 + (warp + 8 * (j & 1)) * 8 + gid;
                int u0 = ub + (j >> 1) * 8 + tig;
                rb2[j][0] = B2[(size_t)n * K2DIM + u0];
                rb2[j][1] = B2[(size_t)n * K2DIM + u0 + 4];
            }
        }

        #pragma unroll
        for (int kk = 0; kk < 2; kk++) {
            uint4 ah[2], al[2];
            uint2 bh[8], bl[8];
            #pragma unroll
            for (int mf = 0; mf < 2; mf++) {
                int slot = kk * 8 + wm * 2 + mf;
                ah[mf] = Ah4[slot * 32 + lane];
                if (TERMS == 3) al[mf] = Al4[slot * 32 + lane];
            }
            #pragma unroll
            for (int nf = 0; nf < 8; nf++) {
                int slot = kk * 16 + wn * 8 + nf;
                bh[nf] = Bh2[slot * 32 + lane];
                if (TERMS >= 2) bl[nf] = Bl2[slot * 32 + lane];
            }
            #pragma unroll
            for (int nf = 0; nf < 8; nf++)
                #pragma unroll
                for (int mf = 0; mf < 2; mf++)
                    MMA_F16(acc[mf][nf], ah[mf], bh[nf]);
            if (TERMS >= 2) {
                #pragma unroll
                for (int nf = 0; nf < 8; nf++)
                    #pragma unroll
                    for (int mf = 0; mf < 2; mf++)
                        MMA_F16(acc[mf][nf], ah[mf], bl[nf]);
            }
            if (TERMS == 3) {
                #pragma unroll
                for (int nf = 0; nf < 8; nf++)
                    #pragma unroll
                    for (int mf = 0; mf < 2; mf++)
                        MMA_F16(acc[mf][nf], al[mf], bh[nf]);
            }
        }
        __syncthreads();
    }

    if (EPI == 0) {
        #pragma unroll
        for (int mf = 0; mf < 2; mf++) {
            const int r0 = m0 + wm * 32 + mf * 16 + gid;
            #pragma unroll
            for (int nf = 0; nf < 8; nf++) {
                const int c = n0 + wn * 64 + nf * 8 + tig * 2;
                *(float2*)(C + (size_t)r0 * N + c) = make_float2(acc[mf][nf][0], acc[mf][nf][1]);
                *(float2*)(C + (size_t)(r0 + 8) * N + c) = make_float2(acc[mf][nf][2], acc[mf][nf][3]);
            }
        }
    } else {
        const int bx = blockIdx.x;
        if (bx < 16) {
            const int h = bx;
            #pragma unroll
            for (int mf = 0; mf < 2; mf++) {
                int rg = (m0 >> 4) + wm * 2 + mf;
                #pragma unroll
                for (int k2 = 0; k2 < 4; k2++) {
                    int kkg = wn * 4 + k2;
                    const float* e = acc[mf][2 * k2];
                    const float* o = acc[mf][2 * k2 + 1];
                    uint4 hv, lv;
                    cvt_h2(e[0], e[1], hv.x, lv.x);
                    cvt_h2(e[2], e[3], hv.y, lv.y);
                    cvt_h2(o[0], o[1], hv.z, lv.z);
                    cvt_h2(o[2], o[3], hv.w, lv.w);
                    size_t idx = ((size_t)(h * 128 + rg) * 8 + kkg) * 32 + lane;
                    g_qh4[idx] = hv;
                    g_ql4[idx] = lv;
                }
            }
        } else if (bx == 16) {
            #pragma unroll
            for (int mf = 0; mf < 2; mf++) {
                int j = m0 + wm * 32 + mf * 16 + gid;
                #pragma unroll
                for (int nf = 0; nf < 8; nf++) {
                    int d2 = wn * 32 + nf * 4 + tig;
                    unsigned h0, l0, h1, l1;
                    cvt_h2(acc[mf][nf][0], acc[mf][nf][1], h0, l0);
                    cvt_h2(acc[mf][nf][2], acc[mf][nf][3], h1, l1);
                    g_kt2[d2 * SEQ + j]     = make_uint2(h0, l0);
                    g_kt2[d2 * SEQ + j + 8] = make_uint2(h1, l1);
                }
            }
        } else {
            #pragma unroll
            for (int mf = 0; mf < 2; mf++) {
                int j = m0 + wm * 32 + mf * 16 + gid;
                #pragma unroll
                for (int nf = 0; nf < 8; nf++) {
                    int d = wn * 64 + nf * 8 + tig * 2;
                    *(float2*)&g_v[(size_t)j * DHEAD + d] =
                        make_float2(acc[mf][nf][0], acc[mf][nf][1]);
                    *(float2*)&g_v[(size_t)(j + 8) * DHEAD + d] =
                        make_float2(acc[mf][nf][2], acc[mf][nf][3]);
                }
            }
        }
    }
}

// ---------------- V j-paired interleaved half2 planes --------------------------
__global__ void vprep_kernel() {
    int t = blockIdx.x * 256 + threadIdx.x;     // 131072
    int d = t & 127, j2 = t >> 7;
    float v0 = g_v[(size_t)(2 * j2) * DHEAD + d];
    float v1 = g_v[(size_t)(2 * j2 + 1) * DHEAD + d];
    unsigned h, l;
    cvt_h2(v0, v1, h, l);
    g_vt2[j2 * DHEAD + d] = make_uint2(h, l);
}

// ---------------- V suffix sums ------------------------------------------------
__global__ void vpart_kernel() {
    int blk = blockIdx.x, d = threadIdx.x;
    float s = 0.f;
    #pragma unroll 8
    for (int r = 0; r < 128; r++)
        s += g_v[(size_t)(blk * 128 + r) * DHEAD + d];
    g_vpart[blk * DHEAD + d] = s;
}
__global__ void vsuf_kernel() {
    int blk = blockIdx.x, d = threadIdx.x;
    float acc = 0.f;
    for (int b = blk + 1; b < 16; b++) acc += g_vpart[b * DHEAD + d];
    #pragma unroll 4
    for (int r = 127; r >= 0; r--) {
        int row = blk * 128 + r;
        g_vsuf[(size_t)row * DHEAD + d] = acc;
        acc += g_v[(size_t)row * DHEAD + d];
    }
}

// ---------------- row-owning fp16 tensor-core flash attention -------------------
// i-tile 128 rows, 8 warps x 16 rows, all 64 j-cols per warp.
// QK x3; PV 1-term (pure fp16 P, fp16 V_hi).  P stays in registers.
__global__ __launch_bounds__(256, 1) void attn_mma_kernel(const float* __restrict__ pos_bias) {
    extern __shared__ float sm[];
    uint2* Kint = (uint2*)sm;
    uint2* Vint = (uint2*)sm + 4352;

    const int h  = blockIdx.y;
    const int ib = gridDim.x - 1 - blockIdx.x;
    const int i0 = ib * 128;
    const int tid = threadIdx.x, lane = tid & 31, warp = tid >> 5;
    const int gid = lane >> 2, tig = lane & 3;

    const int rg = (i0 >> 4) + warp;
    const size_t qbase = ((size_t)(h * 128 + rg) * 8) * 32 + lane;

    const int jl = tid & 63, cb = tid >> 6;
    const int r0g = i0 + warp * 16 + gid, r1g = r0g + 8;
    const int jd = 2 * ib + (warp >> 2);
    const int jbmax = 2 * ib + 1;

    float o[16][4];
    #pragma unroll
    for (int nf = 0; nf < 16; nf++)
        #pragma unroll
        for (int q = 0; q < 4; q++) o[nf][q] = 0.f;
    float m0 = -1e30f, m1 = -1e30f, l0 = 0.f, l1 = 0.f;

    for (int jb = 0; jb <= jbmax; jb++) {
        const int j0 = jb * 64;
        __syncthreads();
        #pragma unroll
        for (int it = 0; it < 16; it++) {
            int d2 = cb * 16 + it;
            Kint[d2 * 68 + jl] = g_kt2[d2 * SEQ + j0 + jl];
        }
        #pragma unroll
        for (int it = 0; it < 16; it++) {
            int idx = it * 256 + tid;
            int j2 = idx >> 7, d = idx & 127;
            Vint[j2 * 132 + d] = g_vt2[(j0 / 2 + j2) * DHEAD + d];
        }
        __syncthreads();

        if (jb > jd) continue;

        // ---- S = Q K^T (fp16 x3)
        float s[8][4];
        #pragma unroll
        for (int nf = 0; nf < 8; nf++)
            #pragma unroll
            for (int q = 0; q < 4; q++) s[nf][q] = 0.f;

        #pragma unroll
        for (int kk = 0; kk < 8; kk++) {
            uint4 qh = g_qh4[qbase + kk * 32];
            uint4 ql = g_ql4[qbase + kk * 32];
            const int kr0 = (kk * 8 + tig) * 68, kr1 = kr0 + 4 * 68;
            uint2 bh[8], bl[8];
            #pragma unroll
            for (int nf = 0; nf < 8; nf++) {
                int col = nf * 8 + gid;
                uint2 kv0 = Kint[kr0 + col];
                uint2 kv1 = Kint[kr1 + col];
                bh[nf] = make_uint2(kv0.x, kv1.x);
                bl[nf] = make_uint2(kv0.y, kv1.y);
            }
            #pragma unroll
            for (int nf = 0; nf < 8; nf++) MMA_F16(s[nf], qh, bh[nf]);
            #pragma unroll
            for (int nf = 0; nf < 8; nf++) MMA_F16(s[nf], qh, bl[nf]);
            #pragma unroll
            for (int nf = 0; nf < 8; nf++) MMA_F16(s[nf], ql, bh[nf]);
        }

        // ---- + pos_bias, causal mask on diagonal block
        const float* pb0 = pos_bias + ((size_t)h * SEQ + r0g) * SEQ + j0 + tig * 2;
        const float* pb1 = pb0 + (size_t)8 * SEQ;
        #pragma unroll
        for (int nf = 0; nf < 8; nf++) {
            float2 b0 = *(const float2*)(pb0 + nf * 8);
            float2 b1 = *(const float2*)(pb1 + nf * 8);
            s[nf][0] += b0.x; s[nf][1] += b0.y;
            s[nf][2] += b1.x; s[nf][3] += b1.y;
        }
        if (jb == jd) {
            #pragma unroll
            for (int nf = 0; nf < 8; nf++) {
                int c = j0 + nf * 8 + tig * 2;
                if (c > r0g)     s[nf][0] = -1e30f;
                if (c + 1 > r0g) s[nf][1] = -1e30f;
                if (c > r1g)     s[nf][2] = -1e30f;
                if (c + 1 > r1g) s[nf][3] = -1e30f;
            }
        }

        // ---- warp-local row max
        float rm0 = -1e30f, rm1 = -1e30f;
        #pragma unroll
        for (int nf = 0; nf < 8; nf++) {
            rm0 = fmaxf(rm0, fmaxf(s[nf][0], s[nf][1]));
            rm1 = fmaxf(rm1, fmaxf(s[nf][2], s[nf][3]));
        }
        rm0 = fmaxf(rm0, __shfl_xor_sync(0xffffffffu, rm0, 1));
        rm0 = fmaxf(rm0, __shfl_xor_sync(0xffffffffu, rm0, 2));
        rm1 = fmaxf(rm1, __shfl_xor_sync(0xffffffffu, rm1, 1));
        rm1 = fmaxf(rm1, __shfl_xor_sync(0xffffffffu, rm1, 2));
        float mn0 = fmaxf(m0, rm0), mn1 = fmaxf(m1, rm1);
        float sc0 = __expf(m0 - mn0), sc1 = __expf(m1 - mn1);

        // ---- exp + in-register fp16 P fragments + row sums
        float rs0 = 0.f, rs1 = 0.f;
        uint4 pah[4];
        #pragma unroll
        for (int c = 0; c < 4; c++) {
            float p00 = __expf(s[2*c][0] - mn0);
            float p01 = __expf(s[2*c][1] - mn0);
            float p02 = __expf(s[2*c][2] - mn1);
            float p03 = __expf(s[2*c][3] - mn1);
            float p10 = __expf(s[2*c+1][0] - mn0);
            float p11 = __expf(s[2*c+1][1] - mn0);
            float p12 = __expf(s[2*c+1][2] - mn1);
            float p13 = __expf(s[2*c+1][3] - mn1);
            rs0 += p00 + p01 + p10 + p11;
            rs1 += p02 + p03 + p12 + p13;
            pah[c].x = cvt_h(p00, p01);
            pah[c].y = cvt_h(p02, p03);
            pah[c].z = cvt_h(p10, p11);
            pah[c].w = cvt_h(p12, p13);
        }
        rs0 += __shfl_xor_sync(0xffffffffu, rs0, 1);
        rs0 += __shfl_xor_sync(0xffffffffu, rs0, 2);
        rs1 += __shfl_xor_sync(0xffffffffu, rs1, 1);
        rs1 += __shfl_xor_sync(0xffffffffu, rs1, 2);
        l0 = l0 * sc0 + rs0;
        l1 = l1 * sc1 + rs1;
        m0 = mn0; m1 = mn1;

        // ---- rescale O, then O += P V (1-term: P_hi * V_hi)
        #pragma unroll
        for (int nf = 0; nf < 16; nf++) {
            o[nf][0] *= sc0; o[nf][1] *= sc0;
            o[nf][2] *= sc1; o[nf][3] *= sc1;
        }
        #pragma unroll
        for (int c = 0; c < 4; c++) {
            const int vr0 = (c * 8 + tig) * 132, vr1 = vr0 + 4 * 132;
            #pragma unroll
            for (int nf = 0; nf < 16; nf++) {
                int dcol = nf * 8 + gid;
                uint2 bh = make_uint2(Vint[vr0 + dcol].x, Vint[vr1 + dcol].x);
                MMA_F16(o[nf], pah[c], bh);
            }
        }
    }

    // ---- finalize with analytic MASK_VALUE tail; write interleaved ao planes
    float cnt0 = (float)(SEQ - 1 - r0g), cnt1 = (float)(SEQ - 1 - r1g);
    float mf0 = fmaxf(m0, MASKVF), mf1 = fmaxf(m1, MASKVF);
    float wu0 = __expf(m0 - mf0),  wu1 = __expf(m1 - mf1);
    float wk0 = __expf(MASKVF - mf0), wk1 = __expf(MASKVF - mf1);
    float iZ0 = 1.f / (l0 * wu0 + cnt0 * wk0);
    float iZ1 = 1.f / (l1 * wu1 + cnt1 * wk1);
    #pragma unroll
    for (int nf = 0; nf < 16; nf++) {
        int dcol = nf * 8 + tig * 2;
        float2 vs0 = *(const float2*)&g_vsuf[(size_t)r0g * DHEAD + dcol];
        float2 vs1 = *(const float2*)&g_vsuf[(size_t)r1g * DHEAD + dcol];
        float o00 = (o[nf][0] * wu0 + wk0 * vs0.x) * iZ0;
        float o01 = (o[nf][1] * wu0 + wk0 * vs0.y) * iZ0;
        float o10 = (o[nf][2] * wu1 + wk1 * vs1.x) * iZ1;
        float o11 = (o[nf][3] * wu1 + wk1 * vs1.y) * iZ1;
        unsigned hw, lw;
        size_t u = (size_t)(h * DHEAD + dcol) >> 1;
        cvt_h2(o00, o01, hw, lw);
        g_ao2[(size_t)r0g * K2DIM + u] = make_uint2(hw, lw);
        cvt_h2(o10, o11, hw, lw);
        g_ao2[(size_t)r1g * K2DIM + u] = make_uint2(hw, lw);
    }
}

// ---------------- launch ---------------------------------------------------------
extern "C" void kernel_launch(void* const* d_in, const int* in_sizes, int n_in,
                              void* d_out, int out_size) {
    (void)in_sizes; (void)n_in; (void)out_size;
    const float* x        = (const float*)d_in[0];
    const float* pos_bias = (const float*)d_in[1];
    const float* gamma    = (const float*)d_in[2];
    const float* wq       = (const float*)d_in[3];
    const float* wk       = (const float*)d_in[4];
    const float* wv       = (const float*)d_in[5];
    const float* wo       = (const float*)d_in[6];
    float* out = (float*)d_out;

    uint2 *xn2_p, *wc2_p, *wo2_p, *ao2_p;
    cudaGetSymbolAddress((void**)&xn2_p, g_xn2);
    cudaGetSymbolAddress((void**)&wc2_p, g_wc2);
    cudaGetSymbolAddress((void**)&wo2_p, g_wo2);
    cudaGetSymbolAddress((void**)&ao2_p, g_ao2);

    const int GEMM_SMEM = 2 * 8192 * 4;      // 65536
    const int ATTN_SMEM = 8576 * 8;          // 68608 (Kint + Vint, uint2)
    cudaFuncSetAttribute((const void*)gemm_h2_kernel<0, 1>, cudaFuncAttributeMaxDynamicSharedMemorySize, GEMM_SMEM);
    cudaFuncSetAttribute((const void*)gemm_h2_kernel<1, 3>, cudaFuncAttributeMaxDynamicSharedMemorySize, GEMM_SMEM);
    cudaFuncSetAttribute((const void*)attn_mma_kernel, cudaFuncAttributeMaxDynamicSharedMemorySize, ATTN_SMEM);

    dim3 tb(32, 8);
    transpose_split_kernel<<<dim3(64, 64), tb>>>(wq, wc2_p, DIMM, SCALEF);
    transpose_split_kernel<<<dim3(4, 64), tb>>>(wk, wc2_p + (size_t)2048 * K2DIM, DHEAD, 1.0f);
    transpose_split_kernel<<<dim3(4, 64), tb>>>(wv, wc2_p + (size_t)2176 * K2DIM, DHEAD, 1.0f);
    transpose_split_kernel<<<dim3(64, 64), tb>>>(wo, wo2_p, DIMM, 1.0f);

    rmsnorm_split_kernel<<<SEQ, 256>>>(x, gamma);

    gemm_h2_kernel<1, 3><<<dim3(18, 16), 256, GEMM_SMEM>>>(xn2_p, wc2_p, nullptr, QKVN);

    vprep_kernel<<<512, 256>>>();
    vpart_kernel<<<16, 128>>>();
    vsuf_kernel<<<16, 128>>>();

    attn_mma_kernel<<<dim3(16, HEADS), 256, ATTN_SMEM>>>(pos_bias);

    gemm_h2_kernel<0, 1><<<dim3(16, 16), 256, GEMM_SMEM>>>(ao2_p, wo2_p, out, DIMM);
}